// round 12
// baseline (speedup 1.0000x reference)
#include <cuda_runtime.h>
#include <math.h>

#define NANCH   8400
#define MAXB    32
#define NCLS    80
#define MAXDET  100
#define NBKT    1024
#define CCAP    256      // chunk capacity (= NMS sort width = blockDim)
#define CAPSEL  280      // preselect target
#define LISTCAP 1024     // per-image candidate list capacity

// ---------------- device scratch (static zero-init; self-cleaning across graph replays) ----------------
__device__ float              g_scores[MAXB * NANCH];
__device__ float4             g_boxes [MAXB * NANCH];
__device__ int                g_labels[MAXB * NANCH];
__device__ int                g_maxabs[MAXB];
__device__ int                g_hist  [MAXB][NBKT];
__device__ unsigned long long g_cand  [MAXB][LISTCAP];
__device__ int                g_ccnt  [MAXB];

__device__ __forceinline__ float sigmoidf_(float x) {
    return 1.0f / (1.0f + expf(-x));
}

__device__ __forceinline__ int score_bucket(float scv) {
    int bkt = (int)(scv * 1024.0f);
    return bkt > NBKT - 1 ? NBKT - 1 : bkt;
}

__device__ __forceinline__ unsigned long long make_key(float scv, unsigned idx) {
    unsigned u = __float_as_uint(scv);
    u = ~(u ^ 0x80000000u);
    return ((unsigned long long)u << 32) | idx;
}

__device__ __forceinline__ float key_score(unsigned long long k) {
    unsigned u = (unsigned)(k >> 32);
    return __uint_as_float((~u) ^ 0x80000000u);
}

__device__ int compute_tcut(const int* hist, int lane) {
    int base = 1023 - 32 * lane;
    int s = 0;
    #pragma unroll 8
    for (int k = 0; k < 32; ++k) s += hist[base - k];
    int cum = s;
    #pragma unroll
    for (int o = 1; o < 32; o <<= 1) {
        int v = __shfl_up_sync(0xFFFFFFFFu, cum, o);
        if (lane >= o) cum += v;
    }
    int tcut = 0;
    unsigned ball = __ballot_sync(0xFFFFFFFFu, cum >= CAPSEL);
    if (ball) {
        int l0 = __ffs(ball) - 1;
        if (lane == l0) {
            int run = cum - s;
            int k = 0;
            for (; k < 32; ++k) {
                run += hist[base - k];
                if (run >= CAPSEL) break;
            }
            tcut = base - k;
        }
        tcut = __shfl_sync(0xFFFFFFFFu, tcut, l0);
    }
    return tcut;
}

// ---------------- decode: 4-way split-class quads, float4 loads, 1 anchor/thread output ----------------
// Quad (4 threads) handles 4 anchors: thread q scans classes q*20..q*20+19 (LDG.128 wide over 4 anchors),
// merge via shfl_xor(1),(2) with lower-quarter-wins ties (= exact first-index argmax).
// Tail threads clamped to last group; stores/atomics guarded.
__global__ void __launch_bounds__(256) k_decode(
    const float* __restrict__ cls0, const float* __restrict__ reg0, const float* __restrict__ obj0,
    const float* __restrict__ cls1, const float* __restrict__ reg1, const float* __restrict__ obj1,
    const float* __restrict__ cls2, const float* __restrict__ reg2, const float* __restrict__ obj2)
{
    __shared__ int s_h[NBKT];
    const int b    = blockIdx.y;
    const int tid  = threadIdx.x;
    const int quar = tid & 3;
    const int g    = blockIdx.x * 64 + (tid >> 2);    // anchor group (4 anchors)
    const bool act = (g < NANCH / 4);
    const int gc   = act ? g : (NANCH / 4 - 1);
    const int a    = gc * 4;
    float m4 = 0.0f;

    ((int4*)s_h)[tid] = make_int4(0, 0, 0, 0);
    __syncthreads();

    const float *cls, *reg, *obj;
    int a0, w, hw; float s;
    if (a < 6400)      { cls = cls0; reg = reg0; obj = obj0; a0 = a;        w = 80; hw = 6400; s = 8.0f;  }
    else if (a < 8000) { cls = cls1; reg = reg1; obj = obj1; a0 = a - 6400; w = 40; hw = 1600; s = 16.0f; }
    else               { cls = cls2; reg = reg2; obj = obj2; a0 = a - 8000; w = 20; hw = 400;  s = 32.0f; }

    const int hw4 = hw >> 2;
    const int q   = a0 >> 2;
    const int lb0 = quar * 20;                         // this thread's class base

    // ---- partial argmax over 20 classes (float4 = 4 anchors wide) ----
    const float4* c4 = (const float4*)(cls + (size_t)b * NCLS * hw) + (size_t)lb0 * hw4 + q;
    float4 v = c4[0];
    float m0 = v.x, m1 = v.y, m2 = v.z, m3 = v.w;
    int   l0 = lb0, l1 = lb0, l2 = lb0, l3 = lb0;
    #pragma unroll 4
    for (int c = 1; c < 20; ++c) {
        v = c4[(size_t)c * hw4];
        if (v.x > m0) { m0 = v.x; l0 = lb0 + c; }
        if (v.y > m1) { m1 = v.y; l1 = lb0 + c; }
        if (v.z > m2) { m2 = v.z; l2 = lb0 + c; }
        if (v.w > m3) { m3 = v.w; l3 = lb0 + c; }
    }

    // ---- merge quads (convergent; lower-quarter wins ties = first-index argmax) ----
    float mm[4] = { m0, m1, m2, m3 };
    int   ll[4] = { l0, l1, l2, l3 };
    #pragma unroll
    for (int step = 1; step <= 2; step <<= 1) {
        const bool amHigh = (quar & step) != 0;
        #pragma unroll
        for (int i = 0; i < 4; ++i) {
            float om = __shfl_xor_sync(0xFFFFFFFFu, mm[i], step);
            int   ol = __shfl_xor_sync(0xFFFFFFFFu, ll[i], step);
            float lom = amHigh ? om : mm[i];
            int   lol = amHigh ? ol : ll[i];
            float him = amHigh ? mm[i] : om;
            int   hil = amHigh ? ll[i] : ol;
            if (him > lom) { mm[i] = him; ll[i] = hil; }
            else           { mm[i] = lom; ll[i] = lol; }
        }
    }

    // ---- reg/obj loads (all 4 load; L2-hit dup) ----
    float4 ov = *((const float4*)(obj + (size_t)b * hw) + q);
    const float* rb = reg + (size_t)b * 4 * hw;
    float4 r0 = *((const float4*)(rb)          + q);
    float4 r1 = *((const float4*)(rb +     hw) + q);
    float4 r2 = *((const float4*)(rb + 2 * hw) + q);
    float4 r3 = *((const float4*)(rb + 3 * hw) + q);

    float oo[4] = { ov.x, ov.y, ov.z, ov.w };
    float rx[4] = { r0.x, r0.y, r0.z, r0.w };
    float ry[4] = { r1.x, r1.y, r1.z, r1.w };
    float rw[4] = { r2.x, r2.y, r2.z, r2.w };
    float rh[4] = { r3.x, r3.y, r3.z, r3.w };

    // ---- decode + store my 1 anchor (index quar) ----
    {
        const int i  = quar;
        const int ai = a0 + i;
        float scv = __fmul_rn(sigmoidf_(mm[i]), sigmoidf_(oo[i]));
        float px = (float)(ai % w) * s;
        float py = (float)(ai / w) * s;
        float cx = __fadd_rn(__fmul_rn(rx[i], s), px);
        float cy = __fadd_rn(__fmul_rn(ry[i], s), py);
        float bw = __fmul_rn(expf(rw[i]), s);
        float bh = __fmul_rn(expf(rh[i]), s);
        float hx = __fmul_rn(bw, 0.5f);
        float hy = __fmul_rn(bh, 0.5f);
        float x1 = __fsub_rn(cx, hx), y1 = __fsub_rn(cy, hy);
        float x2 = __fadd_rn(cx, hx), y2 = __fadd_rn(cy, hy);
        if (act) {
            const size_t gi = (size_t)b * NANCH + a + i;
            g_boxes[gi]  = make_float4(x1, y1, x2, y2);
            g_scores[gi] = scv;
            g_labels[gi] = ll[i];
            m4 = fmaxf(fmaxf(fabsf(x1), fabsf(y1)), fmaxf(fabsf(x2), fabsf(y2)));
            if (scv >= 0.01f)
                atomicAdd(&s_h[score_bucket(scv)], 1);
        }
    }

    #pragma unroll
    for (int o = 16; o > 0; o >>= 1)
        m4 = fmaxf(m4, __shfl_xor_sync(0xFFFFFFFFu, m4, o));
    if ((threadIdx.x & 31) == 0 && m4 > 0.0f)
        atomicMax(&g_maxabs[b], __float_as_int(m4));

    __syncthreads();
    #pragma unroll
    for (int k = tid; k < NBKT; k += 256) {
        int hv = s_h[k];
        if (hv) atomicAdd(&g_hist[b][k], hv);
    }
}

// ---------------- select: compact top-(>=CAPSEL) candidates into per-image list ----------------
__global__ void __launch_bounds__(256) k_select()
{
    __shared__ int s_h[NBKT];
    __shared__ int s_tcut;
    const int b   = blockIdx.y;
    const int tid = threadIdx.x;

    ((int4*)s_h)[tid] = ((const int4*)&g_hist[b][0])[tid];
    __syncthreads();
    if (tid < 32) {
        int t = compute_tcut(s_h, tid);
        if (tid == 0) s_tcut = t;
    }
    __syncthreads();
    const int tcut = s_tcut;

    const int i4 = blockIdx.x * 256 + tid;
    if (i4 < NANCH / 4) {
        float4 s4 = *((const float4*)(g_scores + (size_t)b * NANCH) + i4);
        float sv[4] = { s4.x, s4.y, s4.z, s4.w };
        #pragma unroll
        for (int k = 0; k < 4; ++k) {
            float scv = sv[k];
            if (scv >= 0.01f && score_bucket(scv) >= tcut) {
                int slot = atomicAdd(&g_ccnt[b], 1);
                if (slot < LISTCAP)
                    g_cand[b][slot] = make_key(scv, (unsigned)(i4 * 4 + k));
            }
        }
    }
}

__device__ __forceinline__ unsigned long long shflx64(unsigned long long v, int j) {
    return __shfl_xor_sync(0xFFFFFFFFu, v, j);
}

// exact reference IoU>thr test on offset boxes
__device__ __forceinline__ bool iou_gt(float4 a, float4 bx) {
    float tlx = fmaxf(a.x, bx.x), tly = fmaxf(a.y, bx.y);
    float brx = fminf(a.z, bx.z), bry = fminf(a.w, bx.w);
    float ww = fmaxf(__fsub_rn(brx, tlx), 0.0f);
    float hh = fmaxf(__fsub_rn(bry, tly), 0.0f);
    float inter = __fmul_rn(ww, hh);
    float a1 = __fmul_rn(__fsub_rn(a.z, a.x), __fsub_rn(a.w, a.y));
    float a2 = __fmul_rn(__fsub_rn(bx.z, bx.x), __fsub_rn(bx.w, bx.y));
    float den = __fadd_rn(__fsub_rn(__fadd_rn(a1, a2), inter), 1e-6f);
    return __fdiv_rn(inter, den) > 0.65f;
}

// ---------------- NMS: per-class parallel greedy + rank selection ----------------
__global__ void __launch_bounds__(256) k_nms(float* __restrict__ out, int B)
{
    __shared__ __align__(16) int                s_hist[NBKT];
    __shared__ __align__(16) unsigned long long s_key[CCAP];
    __shared__ __align__(16) float4             s_box[CCAP];
    __shared__ __align__(16) unsigned           s_cmask[NCLS][8];
    __shared__ __align__(16) unsigned char      s_lab8[CCAP];
    __shared__ __align__(16) unsigned char      s_alive[CCAP];
    __shared__ unsigned           s_abits[8];
    __shared__ float4             s_keptb[MAXDET];
    __shared__ unsigned char      s_klab[MAXDET];
    __shared__ int                s_kepti[MAXDET];
    __shared__ float              s_off;
    __shared__ int                s_cnt, s_kc, s_lo, s_hi, s_ptr, s_tcut, s_ccnt;

    const int b    = blockIdx.x;
    const int tid  = threadIdx.x;
    const int wid  = tid >> 5;
    const int lane = tid & 31;
    const size_t base = (size_t)b * NANCH;

    if (tid == 0) {
        s_off = __fadd_rn(__int_as_float(g_maxabs[b]), 1.0f);
        g_maxabs[b] = 0;
        s_ptr = -1;
        s_kc = 0;
        s_ccnt = g_ccnt[b];
        g_ccnt[b] = 0;
    }
    int4 h4;
    {
        int4* gh4 = (int4*)&g_hist[b][0];
        h4 = gh4[tid];
        ((int4*)s_hist)[tid] = h4;
        gh4[tid] = make_int4(0, 0, 0, 0);
    }
    __syncthreads();
    {
        int maxk = -1;
        if (h4.w) maxk = tid * 4 + 3;
        else if (h4.z) maxk = tid * 4 + 2;
        else if (h4.y) maxk = tid * 4 + 1;
        else if (h4.x) maxk = tid * 4;
        #pragma unroll
        for (int o = 16; o > 0; o >>= 1)
            maxk = max(maxk, __shfl_xor_sync(0xFFFFFFFFu, maxk, o));
        if ((tid & 31) == 0) atomicMax(&s_ptr, maxk);
        if (tid < 32) {
            int t = compute_tcut(s_hist, tid);
            if (tid == 0) s_tcut = t;
        }
    }
    __syncthreads();
    const float off = s_off;
    const int   tcut = s_tcut;
    const int   ccnt = s_ccnt;
    const bool  list_ok = (ccnt <= LISTCAP);

    for (;;) {
        if (s_kc >= MAXDET || s_ptr < 0) break;

        if (tid == 0) {
            int acc = 0;
            int hi = s_ptr, p = hi;
            while (p >= 0) {
                int h = s_hist[p];
                if (acc > 0 && acc + h > CCAP) break;
                acc += h; --p;
                if (acc >= CCAP) break;
            }
            s_lo = p + 1; s_hi = hi; s_ptr = p; s_cnt = 0;
        }
        __syncthreads();
        const int lo = s_lo, hi = s_hi;

        // ---- compact (list mode; exact full-sweep fallback) ----
        if (list_ok && lo >= tcut) {
            for (int t = tid; t < ccnt; t += 256) {
                unsigned long long key = g_cand[b][t];
                int bkt = score_bucket(key_score(key));
                if (bkt >= lo && bkt <= hi) {
                    int p = atomicAdd(&s_cnt, 1);
                    if (p < CCAP) s_key[p] = key;
                }
            }
        } else {
            for (int i4 = tid; i4 < NANCH / 4; i4 += 256) {
                float4 s4 = *((const float4*)(g_scores + base) + i4);
                float sv[4] = { s4.x, s4.y, s4.z, s4.w };
                #pragma unroll
                for (int k = 0; k < 4; ++k) {
                    float scv = sv[k];
                    if (scv >= 0.01f) {
                        int bkt = score_bucket(scv);
                        if (bkt >= lo && bkt <= hi) {
                            int p = atomicAdd(&s_cnt, 1);
                            if (p < CCAP) s_key[p] = make_key(scv, (unsigned)(i4 * 4 + k));
                        }
                    }
                }
            }
        }
        __syncthreads();
        int cN = s_cnt; if (cN > CCAP) cN = CCAP;
        if (tid >= cN) s_key[tid] = 0xFFFFFFFFFFFFFFFFull;

        // ---- bitonic sort 256 keys ascending (= score desc, idx asc) ----
        {
            unsigned long long v = s_key[tid];
            #pragma unroll
            for (int k = 2; k <= 32; k <<= 1) {
                bool up = ((tid & k) == 0);
                #pragma unroll
                for (int j = k >> 1; j > 0; j >>= 1) {
                    unsigned long long p = shflx64(v, j);
                    bool keepSmall = (((tid & j) == 0) == up);
                    if (keepSmall ? (p < v) : (p > v)) v = p;
                }
            }
            s_key[tid] = v;
            __syncthreads();
        }
        #pragma unroll
        for (int k = 64; k <= CCAP; k <<= 1) {
            for (int j = k >> 1; j >= 32; j >>= 1) {
                int i = tid, l = i ^ j;
                if (l > i) {
                    unsigned long long A = s_key[i], Bv = s_key[l];
                    bool up = ((i & k) == 0);
                    if ((A > Bv) == up) { s_key[i] = Bv; s_key[l] = A; }
                }
                __syncthreads();
            }
            {
                unsigned long long v = s_key[tid];
                bool up = ((tid & k) == 0);
                #pragma unroll
                for (int j = 16; j > 0; j >>= 1) {
                    unsigned long long p = shflx64(v, j);
                    bool keepSmall = (((tid & j) == 0) == up);
                    if (keepSmall ? (p < v) : (p > v)) v = p;
                }
                s_key[tid] = v;
                __syncthreads();
            }
        }

        // ---- gather boxes/labels; predead vs previous picks; build class masks ----
        const int kc0 = s_kc;
        #pragma unroll
        for (int z = tid; z < NCLS * 8; z += 256) ((unsigned*)s_cmask)[z] = 0u;
        s_alive[tid] = 0;
        __syncthreads();

        if (tid < cN) {
            int idx = (int)(s_key[tid] & 0xFFFFFFFFull);
            float4 mybox = g_boxes[base + idx];
            int mylab = g_labels[base + idx];
            float t = __fmul_rn((float)mylab, off);
            mybox.x = __fadd_rn(mybox.x, t);
            mybox.y = __fadd_rn(mybox.y, t);
            mybox.z = __fadd_rn(mybox.z, t);
            mybox.w = __fadd_rn(mybox.w, t);
            s_box[tid]  = mybox;
            s_lab8[tid] = (unsigned char)mylab;
            int pred = 0;
            for (int j2 = 0; j2 < kc0; ++j2)
                if (s_klab[j2] == (unsigned char)mylab && iou_gt(s_keptb[j2], mybox)) { pred = 1; break; }
            if (!pred)
                atomicOr(&s_cmask[mylab][tid >> 5], 1u << (tid & 31));
        }
        __syncthreads();

        // ---- per-class greedy: 80 independent tiny serial NMS chains in parallel ----
        if (tid < NCLS) {
            unsigned char kl[CCAP];
            int nkl = 0;
            #pragma unroll
            for (int w = 0; w < 8; ++w) {
                unsigned m = s_cmask[tid][w];
                while (m != 0u) {
                    int c = (w << 5) + (__ffs(m) - 1);
                    m &= m - 1u;
                    float4 cb = s_box[c];
                    bool dead = false;
                    for (int j = 0; j < nkl; ++j) {
                        if (iou_gt(s_box[kl[j]], cb)) { dead = true; break; }
                    }
                    if (!dead) {
                        s_alive[c] = 1;
                        kl[nkl++] = (unsigned char)c;
                    }
                }
            }
        }
        __syncthreads();

        // ---- selection: survivor rank via ballots; first (MAXDET-kc0) become picks ----
        {
            unsigned bal = __ballot_sync(0xFFFFFFFFu, s_alive[tid] != 0);
            if (lane == 0) s_abits[wid] = bal;
        }
        __syncthreads();
        {
            int pre = 0;
            #pragma unroll
            for (int w = 0; w < 8; ++w)
                pre += (w < wid) ? __popc(s_abits[w]) : 0;
            if (s_alive[tid]) {
                int rank = pre + __popc(s_abits[wid] & ((lane == 0) ? 0u : (0xFFFFFFFFu >> (32 - lane))));
                int slot = kc0 + rank;
                if (slot < MAXDET) {
                    s_keptb[slot] = s_box[tid];
                    s_klab[slot]  = s_lab8[tid];
                    s_kepti[slot] = (int)(s_key[tid] & 0xFFFFFFFFull);
                }
            }
            if (tid == 0) {
                int tot = 0;
                #pragma unroll
                for (int w = 0; w < 8; ++w) tot += __popc(s_abits[w]);
                int kc = kc0 + tot;
                s_kc = kc > MAXDET ? MAXDET : kc;
            }
        }
        __syncthreads();
    }
    __syncthreads();

    // ---- outputs: boxes | scores | labels | valid ----
    int kc = s_kc;
    float* ob  = out;
    float* osc = out + (size_t)B * MAXDET * 4;
    float* olb = osc + (size_t)B * MAXDET;
    float* ovl = olb + (size_t)B * MAXDET;

    if (tid < MAXDET) {
        int r = tid;
        float4 bx = make_float4(0.f, 0.f, 0.f, 0.f);
        float scv = 0.f, lb = -1.f, vl = 0.f;
        if (r < kc) {
            int idx = s_kepti[r];
            bx = g_boxes[base + idx];
            scv = g_scores[base + idx];
            lb = (float)g_labels[base + idx];
            vl = 1.0f;
        }
        float* obp = ob + ((size_t)b * MAXDET + r) * 4;
        obp[0] = bx.x; obp[1] = bx.y; obp[2] = bx.z; obp[3] = bx.w;
        osc[(size_t)b * MAXDET + r] = scv;
        olb[(size_t)b * MAXDET + r] = lb;
        ovl[(size_t)b * MAXDET + r] = vl;
    }
}

// ---------------- launch ----------------
extern "C" void kernel_launch(void* const* d_in, const int* in_sizes, int n_in,
                              void* d_out, int out_size)
{
    int B = in_sizes[0] / 512000;
    if (B < 1) B = 1;
    if (B > MAXB) B = MAXB;

    const float *cls[3], *reg[3], *obj[3];
    bool grouped = (n_in >= 9) && (in_sizes[1] == B * 128000);
    if (grouped) {
        for (int i = 0; i < 3; ++i) {
            cls[i] = (const float*)d_in[i];
            reg[i] = (const float*)d_in[3 + i];
            obj[i] = (const float*)d_in[6 + i];
        }
    } else {
        for (int i = 0; i < 3; ++i) {
            cls[i] = (const float*)d_in[3 * i];
            reg[i] = (const float*)d_in[3 * i + 1];
            obj[i] = (const float*)d_in[3 * i + 2];
        }
    }

    dim3 gd((2100 * 4 + 255) / 256, B);      // quad-per-group: 33x32 = 1056 CTAs, 256 thr
    k_decode<<<gd, 256>>>(cls[0], reg[0], obj[0],
                          cls[1], reg[1], obj[1],
                          cls[2], reg[2], obj[2]);
    dim3 gs((NANCH / 4 + 255) / 256, B);
    k_select<<<gs, 256>>>();
    k_nms<<<B, 256>>>((float*)d_out, B);
}

// round 13
// speedup vs baseline: 1.1499x; 1.1499x over previous
#include <cuda_runtime.h>
#include <math.h>

#define NANCH   8400
#define MAXB    32
#define NCLS    80
#define MAXDET  100
#define NBKT    1024
#define CCAP    256      // chunk capacity (= NMS sort width = blockDim)
#define CAPSEL  280      // preselect target
#define LISTCAP 1024     // per-image candidate list capacity

// ---------------- device scratch (static zero-init; self-cleaning across graph replays) ----------------
__device__ float              g_scores[MAXB * NANCH];
__device__ float4             g_boxes [MAXB * NANCH];
__device__ int                g_labels[MAXB * NANCH];
__device__ int                g_maxabs[MAXB];
__device__ int                g_hist  [MAXB][NBKT];
__device__ unsigned long long g_cand  [MAXB][LISTCAP];
__device__ int                g_ccnt  [MAXB];

__device__ __forceinline__ float sigmoidf_(float x) {
    return 1.0f / (1.0f + expf(-x));
}

__device__ __forceinline__ int score_bucket(float scv) {
    int bkt = (int)(scv * 1024.0f);
    return bkt > NBKT - 1 ? NBKT - 1 : bkt;
}

__device__ __forceinline__ unsigned long long make_key(float scv, unsigned idx) {
    unsigned u = __float_as_uint(scv);
    u = ~(u ^ 0x80000000u);
    return ((unsigned long long)u << 32) | idx;
}

__device__ __forceinline__ float key_score(unsigned long long k) {
    unsigned u = (unsigned)(k >> 32);
    return __uint_as_float((~u) ^ 0x80000000u);
}

__device__ int compute_tcut(const int* hist, int lane) {
    int base = 1023 - 32 * lane;
    int s = 0;
    #pragma unroll 8
    for (int k = 0; k < 32; ++k) s += hist[base - k];
    int cum = s;
    #pragma unroll
    for (int o = 1; o < 32; o <<= 1) {
        int v = __shfl_up_sync(0xFFFFFFFFu, cum, o);
        if (lane >= o) cum += v;
    }
    int tcut = 0;
    unsigned ball = __ballot_sync(0xFFFFFFFFu, cum >= CAPSEL);
    if (ball) {
        int l0 = __ffs(ball) - 1;
        if (lane == l0) {
            int run = cum - s;
            int k = 0;
            for (; k < 32; ++k) {
                run += hist[base - k];
                if (run >= CAPSEL) break;
            }
            tcut = base - k;
        }
        tcut = __shfl_sync(0xFFFFFFFFu, tcut, l0);
    }
    return tcut;
}

// ---------------- decode: split-class thread pairs (R11 config) + hoisted reg/obj + deeper unroll ----------------
__global__ void __launch_bounds__(256) k_decode(
    const float* __restrict__ cls0, const float* __restrict__ reg0, const float* __restrict__ obj0,
    const float* __restrict__ cls1, const float* __restrict__ reg1, const float* __restrict__ obj1,
    const float* __restrict__ cls2, const float* __restrict__ reg2, const float* __restrict__ obj2)
{
    __shared__ int s_h[NBKT];
    const int b    = blockIdx.y;
    const int tid  = threadIdx.x;
    const int half = tid & 1;
    const int g    = blockIdx.x * 128 + (tid >> 1);   // anchor group (4 anchors)
    const bool act = (g < NANCH / 4);
    const int gc   = act ? g : (NANCH / 4 - 1);       // clamp: tail threads compute redundantly
    const int a    = gc * 4;
    float m4 = 0.0f;

    ((int4*)s_h)[tid] = make_int4(0, 0, 0, 0);
    __syncthreads();

    const float *cls, *reg, *obj;
    int a0, w, hw; float s;
    if (a < 6400)      { cls = cls0; reg = reg0; obj = obj0; a0 = a;        w = 80; hw = 6400; s = 8.0f;  }
    else if (a < 8000) { cls = cls1; reg = reg1; obj = obj1; a0 = a - 6400; w = 40; hw = 1600; s = 16.0f; }
    else               { cls = cls2; reg = reg2; obj = obj2; a0 = a - 8000; w = 20; hw = 400;  s = 32.0f; }

    const int hw4 = hw >> 2;
    const int q   = a0 >> 2;
    const int lb0 = half * 40;

    // ---- hoisted reg/obj loads: in flight during the whole argmax chain ----
    float4 ov = *((const float4*)(obj + (size_t)b * hw) + q);
    const float* rb = reg + (size_t)b * 4 * hw;
    float4 r0 = *((const float4*)(rb)          + q);
    float4 r1 = *((const float4*)(rb +     hw) + q);
    float4 r2 = *((const float4*)(rb + 2 * hw) + q);
    float4 r3 = *((const float4*)(rb + 3 * hw) + q);

    // ---- partial argmax over 40 classes (float4 = 4 anchors wide), deep unroll for MLP ----
    const float4* c4 = (const float4*)(cls + (size_t)b * NCLS * hw) + (size_t)lb0 * hw4 + q;
    float4 v = c4[0];
    float m0 = v.x, m1 = v.y, m2 = v.z, m3 = v.w;
    int   l0 = lb0, l1 = lb0, l2 = lb0, l3 = lb0;
    #pragma unroll 8
    for (int c = 1; c < 40; ++c) {
        v = c4[(size_t)c * hw4];
        if (v.x > m0) { m0 = v.x; l0 = lb0 + c; }
        if (v.y > m1) { m1 = v.y; l1 = lb0 + c; }
        if (v.z > m2) { m2 = v.z; l2 = lb0 + c; }
        if (v.w > m3) { m3 = v.w; l3 = lb0 + c; }
    }

    // ---- merge halves (convergent; low half wins ties = first-index argmax) ----
    float mm[4] = { m0, m1, m2, m3 };
    int   ll[4] = { l0, l1, l2, l3 };
    #pragma unroll
    for (int i = 0; i < 4; ++i) {
        float om = __shfl_xor_sync(0xFFFFFFFFu, mm[i], 1);
        int   ol = __shfl_xor_sync(0xFFFFFFFFu, ll[i], 1);
        float lom = half ? om : mm[i];
        int   lol = half ? ol : ll[i];
        float him = half ? mm[i] : om;
        int   hil = half ? ll[i] : ol;
        if (him > lom) { mm[i] = him; ll[i] = hil; }
        else           { mm[i] = lom; ll[i] = lol; }
    }

    float oo[4] = { ov.x, ov.y, ov.z, ov.w };
    float rx[4] = { r0.x, r0.y, r0.z, r0.w };
    float ry[4] = { r1.x, r1.y, r1.z, r1.w };
    float rw[4] = { r2.x, r2.y, r2.z, r2.w };
    float rh[4] = { r3.x, r3.y, r3.z, r3.w };

    // ---- decode + store my 2 anchors (half*2, half*2+1); stores guarded by act ----
    const int i0 = half * 2;
    const size_t mybase = (size_t)b * NANCH + a + i0;
    float sc[2];
    int   lo2[2];
    #pragma unroll
    for (int k = 0; k < 2; ++k) {
        int i = i0 + k;
        sc[k]  = __fmul_rn(sigmoidf_(mm[i]), sigmoidf_(oo[i]));
        lo2[k] = ll[i];
        int ai = a0 + i;
        float px = (float)(ai % w) * s;
        float py = (float)(ai / w) * s;
        float cx = __fadd_rn(__fmul_rn(rx[i], s), px);
        float cy = __fadd_rn(__fmul_rn(ry[i], s), py);
        float bw = __fmul_rn(expf(rw[i]), s);
        float bh = __fmul_rn(expf(rh[i]), s);
        float hx = __fmul_rn(bw, 0.5f);
        float hy = __fmul_rn(bh, 0.5f);
        float x1 = __fsub_rn(cx, hx), y1 = __fsub_rn(cy, hy);
        float x2 = __fadd_rn(cx, hx), y2 = __fadd_rn(cy, hy);
        if (act) {
            g_boxes[mybase + k] = make_float4(x1, y1, x2, y2);
            m4 = fmaxf(m4, fmaxf(fmaxf(fabsf(x1), fabsf(y1)), fmaxf(fabsf(x2), fabsf(y2))));
            if (sc[k] >= 0.01f)
                atomicAdd(&s_h[score_bucket(sc[k])], 1);
        }
    }
    if (act) {
        *((float2*)(g_scores + mybase)) = make_float2(sc[0], sc[1]);
        *((int2*)(g_labels + mybase))   = make_int2(lo2[0], lo2[1]);
    }

    #pragma unroll
    for (int o = 16; o > 0; o >>= 1)
        m4 = fmaxf(m4, __shfl_xor_sync(0xFFFFFFFFu, m4, o));
    if ((threadIdx.x & 31) == 0 && m4 > 0.0f)
        atomicMax(&g_maxabs[b], __float_as_int(m4));

    __syncthreads();
    #pragma unroll
    for (int k = tid; k < NBKT; k += 256) {
        int hv = s_h[k];
        if (hv) atomicAdd(&g_hist[b][k], hv);
    }
}

// ---------------- select: compact top-(>=CAPSEL) candidates into per-image list ----------------
__global__ void __launch_bounds__(256) k_select()
{
    __shared__ int s_h[NBKT];
    __shared__ int s_tcut;
    const int b   = blockIdx.y;
    const int tid = threadIdx.x;

    ((int4*)s_h)[tid] = ((const int4*)&g_hist[b][0])[tid];
    __syncthreads();
    if (tid < 32) {
        int t = compute_tcut(s_h, tid);
        if (tid == 0) s_tcut = t;
    }
    __syncthreads();
    const int tcut = s_tcut;

    const int i4 = blockIdx.x * 256 + tid;
    if (i4 < NANCH / 4) {
        float4 s4 = *((const float4*)(g_scores + (size_t)b * NANCH) + i4);
        float sv[4] = { s4.x, s4.y, s4.z, s4.w };
        #pragma unroll
        for (int k = 0; k < 4; ++k) {
            float scv = sv[k];
            if (scv >= 0.01f && score_bucket(scv) >= tcut) {
                int slot = atomicAdd(&g_ccnt[b], 1);
                if (slot < LISTCAP)
                    g_cand[b][slot] = make_key(scv, (unsigned)(i4 * 4 + k));
            }
        }
    }
}

__device__ __forceinline__ unsigned long long shflx64(unsigned long long v, int j) {
    return __shfl_xor_sync(0xFFFFFFFFu, v, j);
}

// exact reference IoU>thr test on offset boxes
__device__ __forceinline__ bool iou_gt(float4 a, float4 bx) {
    float tlx = fmaxf(a.x, bx.x), tly = fmaxf(a.y, bx.y);
    float brx = fminf(a.z, bx.z), bry = fminf(a.w, bx.w);
    float ww = fmaxf(__fsub_rn(brx, tlx), 0.0f);
    float hh = fmaxf(__fsub_rn(bry, tly), 0.0f);
    float inter = __fmul_rn(ww, hh);
    float a1 = __fmul_rn(__fsub_rn(a.z, a.x), __fsub_rn(a.w, a.y));
    float a2 = __fmul_rn(__fsub_rn(bx.z, bx.x), __fsub_rn(bx.w, bx.y));
    float den = __fadd_rn(__fsub_rn(__fadd_rn(a1, a2), inter), 1e-6f);
    return __fdiv_rn(inter, den) > 0.65f;
}

// ---------------- NMS: per-class parallel greedy + rank selection ----------------
__global__ void __launch_bounds__(256) k_nms(float* __restrict__ out, int B)
{
    __shared__ __align__(16) int                s_hist[NBKT];
    __shared__ __align__(16) unsigned long long s_key[CCAP];
    __shared__ __align__(16) float4             s_box[CCAP];
    __shared__ __align__(16) unsigned           s_cmask[NCLS][8];
    __shared__ __align__(16) unsigned char      s_lab8[CCAP];
    __shared__ __align__(16) unsigned char      s_alive[CCAP];
    __shared__ unsigned           s_abits[8];
    __shared__ float4             s_keptb[MAXDET];
    __shared__ unsigned char      s_klab[MAXDET];
    __shared__ int                s_kepti[MAXDET];
    __shared__ float              s_off;
    __shared__ int                s_cnt, s_kc, s_lo, s_hi, s_ptr, s_tcut, s_ccnt;

    const int b    = blockIdx.x;
    const int tid  = threadIdx.x;
    const int wid  = tid >> 5;
    const int lane = tid & 31;
    const size_t base = (size_t)b * NANCH;

    if (tid == 0) {
        s_off = __fadd_rn(__int_as_float(g_maxabs[b]), 1.0f);
        g_maxabs[b] = 0;
        s_ptr = -1;
        s_kc = 0;
        s_ccnt = g_ccnt[b];
        g_ccnt[b] = 0;
    }
    int4 h4;
    {
        int4* gh4 = (int4*)&g_hist[b][0];
        h4 = gh4[tid];
        ((int4*)s_hist)[tid] = h4;
        gh4[tid] = make_int4(0, 0, 0, 0);
    }
    __syncthreads();
    {
        int maxk = -1;
        if (h4.w) maxk = tid * 4 + 3;
        else if (h4.z) maxk = tid * 4 + 2;
        else if (h4.y) maxk = tid * 4 + 1;
        else if (h4.x) maxk = tid * 4;
        #pragma unroll
        for (int o = 16; o > 0; o >>= 1)
            maxk = max(maxk, __shfl_xor_sync(0xFFFFFFFFu, maxk, o));
        if ((tid & 31) == 0) atomicMax(&s_ptr, maxk);
        if (tid < 32) {
            int t = compute_tcut(s_hist, tid);
            if (tid == 0) s_tcut = t;
        }
    }
    __syncthreads();
    const float off = s_off;
    const int   tcut = s_tcut;
    const int   ccnt = s_ccnt;
    const bool  list_ok = (ccnt <= LISTCAP);

    for (;;) {
        if (s_kc >= MAXDET || s_ptr < 0) break;

        if (tid == 0) {
            int acc = 0;
            int hi = s_ptr, p = hi;
            while (p >= 0) {
                int h = s_hist[p];
                if (acc > 0 && acc + h > CCAP) break;
                acc += h; --p;
                if (acc >= CCAP) break;
            }
            s_lo = p + 1; s_hi = hi; s_ptr = p; s_cnt = 0;
        }
        __syncthreads();
        const int lo = s_lo, hi = s_hi;

        // ---- compact (list mode; exact full-sweep fallback) ----
        if (list_ok && lo >= tcut) {
            for (int t = tid; t < ccnt; t += 256) {
                unsigned long long key = g_cand[b][t];
                int bkt = score_bucket(key_score(key));
                if (bkt >= lo && bkt <= hi) {
                    int p = atomicAdd(&s_cnt, 1);
                    if (p < CCAP) s_key[p] = key;
                }
            }
        } else {
            for (int i4 = tid; i4 < NANCH / 4; i4 += 256) {
                float4 s4 = *((const float4*)(g_scores + base) + i4);
                float sv[4] = { s4.x, s4.y, s4.z, s4.w };
                #pragma unroll
                for (int k = 0; k < 4; ++k) {
                    float scv = sv[k];
                    if (scv >= 0.01f) {
                        int bkt = score_bucket(scv);
                        if (bkt >= lo && bkt <= hi) {
                            int p = atomicAdd(&s_cnt, 1);
                            if (p < CCAP) s_key[p] = make_key(scv, (unsigned)(i4 * 4 + k));
                        }
                    }
                }
            }
        }
        __syncthreads();
        int cN = s_cnt; if (cN > CCAP) cN = CCAP;
        if (tid >= cN) s_key[tid] = 0xFFFFFFFFFFFFFFFFull;

        // ---- bitonic sort 256 keys ascending (= score desc, idx asc) ----
        {
            unsigned long long v = s_key[tid];
            #pragma unroll
            for (int k = 2; k <= 32; k <<= 1) {
                bool up = ((tid & k) == 0);
                #pragma unroll
                for (int j = k >> 1; j > 0; j >>= 1) {
                    unsigned long long p = shflx64(v, j);
                    bool keepSmall = (((tid & j) == 0) == up);
                    if (keepSmall ? (p < v) : (p > v)) v = p;
                }
            }
            s_key[tid] = v;
            __syncthreads();
        }
        #pragma unroll
        for (int k = 64; k <= CCAP; k <<= 1) {
            for (int j = k >> 1; j >= 32; j >>= 1) {
                int i = tid, l = i ^ j;
                if (l > i) {
                    unsigned long long A = s_key[i], Bv = s_key[l];
                    bool up = ((i & k) == 0);
                    if ((A > Bv) == up) { s_key[i] = Bv; s_key[l] = A; }
                }
                __syncthreads();
            }
            {
                unsigned long long v = s_key[tid];
                bool up = ((tid & k) == 0);
                #pragma unroll
                for (int j = 16; j > 0; j >>= 1) {
                    unsigned long long p = shflx64(v, j);
                    bool keepSmall = (((tid & j) == 0) == up);
                    if (keepSmall ? (p < v) : (p > v)) v = p;
                }
                s_key[tid] = v;
                __syncthreads();
            }
        }

        // ---- gather boxes/labels; predead vs previous picks; build class masks ----
        const int kc0 = s_kc;
        #pragma unroll
        for (int z = tid; z < NCLS * 8; z += 256) ((unsigned*)s_cmask)[z] = 0u;
        s_alive[tid] = 0;
        __syncthreads();

        if (tid < cN) {
            int idx = (int)(s_key[tid] & 0xFFFFFFFFull);
            float4 mybox = g_boxes[base + idx];
            int mylab = g_labels[base + idx];
            float t = __fmul_rn((float)mylab, off);
            mybox.x = __fadd_rn(mybox.x, t);
            mybox.y = __fadd_rn(mybox.y, t);
            mybox.z = __fadd_rn(mybox.z, t);
            mybox.w = __fadd_rn(mybox.w, t);
            s_box[tid]  = mybox;
            s_lab8[tid] = (unsigned char)mylab;
            int pred = 0;
            for (int j2 = 0; j2 < kc0; ++j2)
                if (s_klab[j2] == (unsigned char)mylab && iou_gt(s_keptb[j2], mybox)) { pred = 1; break; }
            if (!pred)
                atomicOr(&s_cmask[mylab][tid >> 5], 1u << (tid & 31));
        }
        __syncthreads();

        // ---- per-class greedy: 80 independent tiny serial NMS chains in parallel ----
        if (tid < NCLS) {
            unsigned char kl[CCAP];
            int nkl = 0;
            #pragma unroll
            for (int w = 0; w < 8; ++w) {
                unsigned m = s_cmask[tid][w];
                while (m != 0u) {
                    int c = (w << 5) + (__ffs(m) - 1);
                    m &= m - 1u;
                    float4 cb = s_box[c];
                    bool dead = false;
                    for (int j = 0; j < nkl; ++j) {
                        if (iou_gt(s_box[kl[j]], cb)) { dead = true; break; }
                    }
                    if (!dead) {
                        s_alive[c] = 1;
                        kl[nkl++] = (unsigned char)c;
                    }
                }
            }
        }
        __syncthreads();

        // ---- selection: survivor rank via ballots; first (MAXDET-kc0) become picks ----
        {
            unsigned bal = __ballot_sync(0xFFFFFFFFu, s_alive[tid] != 0);
            if (lane == 0) s_abits[wid] = bal;
        }
        __syncthreads();
        {
            int pre = 0;
            #pragma unroll
            for (int w = 0; w < 8; ++w)
                pre += (w < wid) ? __popc(s_abits[w]) : 0;
            if (s_alive[tid]) {
                int rank = pre + __popc(s_abits[wid] & ((lane == 0) ? 0u : (0xFFFFFFFFu >> (32 - lane))));
                int slot = kc0 + rank;
                if (slot < MAXDET) {
                    s_keptb[slot] = s_box[tid];
                    s_klab[slot]  = s_lab8[tid];
                    s_kepti[slot] = (int)(s_key[tid] & 0xFFFFFFFFull);
                }
            }
            if (tid == 0) {
                int tot = 0;
                #pragma unroll
                for (int w = 0; w < 8; ++w) tot += __popc(s_abits[w]);
                int kc = kc0 + tot;
                s_kc = kc > MAXDET ? MAXDET : kc;
            }
        }
        __syncthreads();
    }
    __syncthreads();

    // ---- outputs: boxes | scores | labels | valid ----
    int kc = s_kc;
    float* ob  = out;
    float* osc = out + (size_t)B * MAXDET * 4;
    float* olb = osc + (size_t)B * MAXDET;
    float* ovl = olb + (size_t)B * MAXDET;

    if (tid < MAXDET) {
        int r = tid;
        float4 bx = make_float4(0.f, 0.f, 0.f, 0.f);
        float scv = 0.f, lb = -1.f, vl = 0.f;
        if (r < kc) {
            int idx = s_kepti[r];
            bx = g_boxes[base + idx];
            scv = g_scores[base + idx];
            lb = (float)g_labels[base + idx];
            vl = 1.0f;
        }
        float* obp = ob + ((size_t)b * MAXDET + r) * 4;
        obp[0] = bx.x; obp[1] = bx.y; obp[2] = bx.z; obp[3] = bx.w;
        osc[(size_t)b * MAXDET + r] = scv;
        olb[(size_t)b * MAXDET + r] = lb;
        ovl[(size_t)b * MAXDET + r] = vl;
    }
}

// ---------------- launch ----------------
extern "C" void kernel_launch(void* const* d_in, const int* in_sizes, int n_in,
                              void* d_out, int out_size)
{
    int B = in_sizes[0] / 512000;
    if (B < 1) B = 1;
    if (B > MAXB) B = MAXB;

    const float *cls[3], *reg[3], *obj[3];
    bool grouped = (n_in >= 9) && (in_sizes[1] == B * 128000);
    if (grouped) {
        for (int i = 0; i < 3; ++i) {
            cls[i] = (const float*)d_in[i];
            reg[i] = (const float*)d_in[3 + i];
            obj[i] = (const float*)d_in[6 + i];
        }
    } else {
        for (int i = 0; i < 3; ++i) {
            cls[i] = (const float*)d_in[3 * i];
            reg[i] = (const float*)d_in[3 * i + 1];
            obj[i] = (const float*)d_in[3 * i + 2];
        }
    }

    dim3 gd((2100 + 127) / 128, B);          // pair-per-group (R11 config): 544 CTAs
    k_decode<<<gd, 256>>>(cls[0], reg[0], obj[0],
                          cls[1], reg[1], obj[1],
                          cls[2], reg[2], obj[2]);
    dim3 gs((NANCH / 4 + 255) / 256, B);
    k_select<<<gs, 256>>>();
    k_nms<<<B, 256>>>((float*)d_out, B);
}

// round 14
// speedup vs baseline: 1.2296x; 1.0693x over previous
#include <cuda_runtime.h>
#include <math.h>

#define NANCH   8400
#define MAXB    32
#define NCLS    80
#define MAXDET  100
#define NBKT    1024
#define CCAP    256      // chunk capacity (= NMS sort width = blockDim)

// ---------------- device scratch (static zero-init; self-cleaning across graph replays) ----------------
__device__ float  g_scores[MAXB * NANCH];
__device__ float4 g_boxes [MAXB * NANCH];
__device__ int    g_labels[MAXB * NANCH];
__device__ int    g_maxabs[MAXB];
__device__ int    g_hist  [MAXB][NBKT];

__device__ __forceinline__ float sigmoidf_(float x) {
    return 1.0f / (1.0f + expf(-x));
}

__device__ __forceinline__ int score_bucket(float scv) {
    int bkt = (int)(scv * 1024.0f);
    return bkt > NBKT - 1 ? NBKT - 1 : bkt;
}

__device__ __forceinline__ unsigned long long make_key(float scv, unsigned idx) {
    unsigned u = __float_as_uint(scv);
    u = ~(u ^ 0x80000000u);
    return ((unsigned long long)u << 32) | idx;
}

// ---------------- decode: split-class thread pairs + hoisted reg/obj + deep unroll (R13 best) ----------------
__global__ void __launch_bounds__(256) k_decode(
    const float* __restrict__ cls0, const float* __restrict__ reg0, const float* __restrict__ obj0,
    const float* __restrict__ cls1, const float* __restrict__ reg1, const float* __restrict__ obj1,
    const float* __restrict__ cls2, const float* __restrict__ reg2, const float* __restrict__ obj2)
{
    __shared__ int s_h[NBKT];
    const int b    = blockIdx.y;
    const int tid  = threadIdx.x;
    const int half = tid & 1;
    const int g    = blockIdx.x * 128 + (tid >> 1);   // anchor group (4 anchors)
    const bool act = (g < NANCH / 4);
    const int gc   = act ? g : (NANCH / 4 - 1);       // clamp: tail threads compute redundantly
    const int a    = gc * 4;
    float m4 = 0.0f;

    ((int4*)s_h)[tid] = make_int4(0, 0, 0, 0);
    __syncthreads();

    const float *cls, *reg, *obj;
    int a0, w, hw; float s;
    if (a < 6400)      { cls = cls0; reg = reg0; obj = obj0; a0 = a;        w = 80; hw = 6400; s = 8.0f;  }
    else if (a < 8000) { cls = cls1; reg = reg1; obj = obj1; a0 = a - 6400; w = 40; hw = 1600; s = 16.0f; }
    else               { cls = cls2; reg = reg2; obj = obj2; a0 = a - 8000; w = 20; hw = 400;  s = 32.0f; }

    const int hw4 = hw >> 2;
    const int q   = a0 >> 2;
    const int lb0 = half * 40;

    // hoisted reg/obj loads: in flight during the whole argmax chain
    float4 ov = *((const float4*)(obj + (size_t)b * hw) + q);
    const float* rb = reg + (size_t)b * 4 * hw;
    float4 r0 = *((const float4*)(rb)          + q);
    float4 r1 = *((const float4*)(rb +     hw) + q);
    float4 r2 = *((const float4*)(rb + 2 * hw) + q);
    float4 r3 = *((const float4*)(rb + 3 * hw) + q);

    // partial argmax over 40 classes (float4 = 4 anchors wide)
    const float4* c4 = (const float4*)(cls + (size_t)b * NCLS * hw) + (size_t)lb0 * hw4 + q;
    float4 v = c4[0];
    float m0 = v.x, m1 = v.y, m2 = v.z, m3 = v.w;
    int   l0 = lb0, l1 = lb0, l2 = lb0, l3 = lb0;
    #pragma unroll 8
    for (int c = 1; c < 40; ++c) {
        v = c4[(size_t)c * hw4];
        if (v.x > m0) { m0 = v.x; l0 = lb0 + c; }
        if (v.y > m1) { m1 = v.y; l1 = lb0 + c; }
        if (v.z > m2) { m2 = v.z; l2 = lb0 + c; }
        if (v.w > m3) { m3 = v.w; l3 = lb0 + c; }
    }

    // merge halves (convergent; low half wins ties = first-index argmax)
    float mm[4] = { m0, m1, m2, m3 };
    int   ll[4] = { l0, l1, l2, l3 };
    #pragma unroll
    for (int i = 0; i < 4; ++i) {
        float om = __shfl_xor_sync(0xFFFFFFFFu, mm[i], 1);
        int   ol = __shfl_xor_sync(0xFFFFFFFFu, ll[i], 1);
        float lom = half ? om : mm[i];
        int   lol = half ? ol : ll[i];
        float him = half ? mm[i] : om;
        int   hil = half ? ll[i] : ol;
        if (him > lom) { mm[i] = him; ll[i] = hil; }
        else           { mm[i] = lom; ll[i] = lol; }
    }

    float oo[4] = { ov.x, ov.y, ov.z, ov.w };
    float rx[4] = { r0.x, r0.y, r0.z, r0.w };
    float ry[4] = { r1.x, r1.y, r1.z, r1.w };
    float rw[4] = { r2.x, r2.y, r2.z, r2.w };
    float rh[4] = { r3.x, r3.y, r3.z, r3.w };

    // decode + store my 2 anchors; stores guarded by act
    const int i0 = half * 2;
    const size_t mybase = (size_t)b * NANCH + a + i0;
    float sc[2];
    int   lo2[2];
    #pragma unroll
    for (int k = 0; k < 2; ++k) {
        int i = i0 + k;
        sc[k]  = __fmul_rn(sigmoidf_(mm[i]), sigmoidf_(oo[i]));
        lo2[k] = ll[i];
        int ai = a0 + i;
        float px = (float)(ai % w) * s;
        float py = (float)(ai / w) * s;
        float cx = __fadd_rn(__fmul_rn(rx[i], s), px);
        float cy = __fadd_rn(__fmul_rn(ry[i], s), py);
        float bw = __fmul_rn(expf(rw[i]), s);
        float bh = __fmul_rn(expf(rh[i]), s);
        float hx = __fmul_rn(bw, 0.5f);
        float hy = __fmul_rn(bh, 0.5f);
        float x1 = __fsub_rn(cx, hx), y1 = __fsub_rn(cy, hy);
        float x2 = __fadd_rn(cx, hx), y2 = __fadd_rn(cy, hy);
        if (act) {
            g_boxes[mybase + k] = make_float4(x1, y1, x2, y2);
            m4 = fmaxf(m4, fmaxf(fmaxf(fabsf(x1), fabsf(y1)), fmaxf(fabsf(x2), fabsf(y2))));
            if (sc[k] >= 0.01f)
                atomicAdd(&s_h[score_bucket(sc[k])], 1);
        }
    }
    if (act) {
        *((float2*)(g_scores + mybase)) = make_float2(sc[0], sc[1]);
        *((int2*)(g_labels + mybase))   = make_int2(lo2[0], lo2[1]);
    }

    #pragma unroll
    for (int o = 16; o > 0; o >>= 1)
        m4 = fmaxf(m4, __shfl_xor_sync(0xFFFFFFFFu, m4, o));
    if ((threadIdx.x & 31) == 0 && m4 > 0.0f)
        atomicMax(&g_maxabs[b], __float_as_int(m4));

    __syncthreads();
    #pragma unroll
    for (int k = tid; k < NBKT; k += 256) {
        int hv = s_h[k];
        if (hv) atomicAdd(&g_hist[b][k], hv);
    }
}

__device__ __forceinline__ unsigned long long shflx64(unsigned long long v, int j) {
    return __shfl_xor_sync(0xFFFFFFFFu, v, j);
}

// exact reference IoU>thr test on offset boxes
__device__ __forceinline__ bool iou_gt(float4 a, float4 bx) {
    float tlx = fmaxf(a.x, bx.x), tly = fmaxf(a.y, bx.y);
    float brx = fminf(a.z, bx.z), bry = fminf(a.w, bx.w);
    float ww = fmaxf(__fsub_rn(brx, tlx), 0.0f);
    float hh = fmaxf(__fsub_rn(bry, tly), 0.0f);
    float inter = __fmul_rn(ww, hh);
    float a1 = __fmul_rn(__fsub_rn(a.z, a.x), __fsub_rn(a.w, a.y));
    float a2 = __fmul_rn(__fsub_rn(bx.z, bx.x), __fsub_rn(bx.w, bx.y));
    float den = __fadd_rn(__fsub_rn(__fadd_rn(a1, a2), inter), 1e-6f);
    return __fdiv_rn(inter, den) > 0.65f;
}

// ---------------- NMS: full-sweep compact -> sort -> per-class parallel greedy -> rank selection ----------------
__global__ void __launch_bounds__(256) k_nms(float* __restrict__ out, int B)
{
    __shared__ __align__(16) int                s_hist[NBKT];
    __shared__ __align__(16) unsigned long long s_key[CCAP];
    __shared__ __align__(16) float4             s_box[CCAP];
    __shared__ __align__(16) unsigned           s_cmask[NCLS][8];
    __shared__ __align__(16) unsigned char      s_lab8[CCAP];
    __shared__ __align__(16) unsigned char      s_alive[CCAP];
    __shared__ unsigned           s_abits[8];
    __shared__ float4             s_keptb[MAXDET];
    __shared__ unsigned char      s_klab[MAXDET];
    __shared__ int                s_kepti[MAXDET];
    __shared__ float              s_off;
    __shared__ int                s_cnt, s_kc, s_lo, s_hi, s_ptr;

    const int b    = blockIdx.x;
    const int tid  = threadIdx.x;
    const int wid  = tid >> 5;
    const int lane = tid & 31;
    const size_t base = (size_t)b * NANCH;

    if (tid == 0) {
        s_off = __fadd_rn(__int_as_float(g_maxabs[b]), 1.0f);
        g_maxabs[b] = 0;
        s_ptr = -1;
        s_kc = 0;
    }
    int4 h4;
    {
        int4* gh4 = (int4*)&g_hist[b][0];
        h4 = gh4[tid];
        ((int4*)s_hist)[tid] = h4;
        gh4[tid] = make_int4(0, 0, 0, 0);
    }
    __syncthreads();
    {
        int maxk = -1;
        if (h4.w) maxk = tid * 4 + 3;
        else if (h4.z) maxk = tid * 4 + 2;
        else if (h4.y) maxk = tid * 4 + 1;
        else if (h4.x) maxk = tid * 4;
        #pragma unroll
        for (int o = 16; o > 0; o >>= 1)
            maxk = max(maxk, __shfl_xor_sync(0xFFFFFFFFu, maxk, o));
        if ((tid & 31) == 0) atomicMax(&s_ptr, maxk);
    }
    __syncthreads();
    const float off = s_off;

    for (;;) {
        if (s_kc >= MAXDET || s_ptr < 0) break;

        // chunk range walk (starts at highest nonempty bucket)
        if (tid == 0) {
            int acc = 0;
            int hi = s_ptr, p = hi;
            while (p >= 0) {
                int h = s_hist[p];
                if (acc > 0 && acc + h > CCAP) break;
                acc += h; --p;
                if (acc >= CCAP) break;
            }
            s_lo = p + 1; s_hi = hi; s_ptr = p; s_cnt = 0;
        }
        __syncthreads();
        const int lo = s_lo, hi = s_hi;

        // ---- compact: full vectorized sweep over L2-resident scores (exact) ----
        for (int i4 = tid; i4 < NANCH / 4; i4 += 256) {
            float4 s4 = *((const float4*)(g_scores + base) + i4);
            float sv[4] = { s4.x, s4.y, s4.z, s4.w };
            #pragma unroll
            for (int k = 0; k < 4; ++k) {
                float scv = sv[k];
                if (scv >= 0.01f) {
                    int bkt = score_bucket(scv);
                    if (bkt >= lo && bkt <= hi) {
                        int p = atomicAdd(&s_cnt, 1);
                        if (p < CCAP) s_key[p] = make_key(scv, (unsigned)(i4 * 4 + k));
                    }
                }
            }
        }
        __syncthreads();
        int cN = s_cnt; if (cN > CCAP) cN = CCAP;
        if (tid >= cN) s_key[tid] = 0xFFFFFFFFFFFFFFFFull;

        // ---- bitonic sort 256 keys ascending (= score desc, idx asc) ----
        {
            unsigned long long v = s_key[tid];
            #pragma unroll
            for (int k = 2; k <= 32; k <<= 1) {
                bool up = ((tid & k) == 0);
                #pragma unroll
                for (int j = k >> 1; j > 0; j >>= 1) {
                    unsigned long long p = shflx64(v, j);
                    bool keepSmall = (((tid & j) == 0) == up);
                    if (keepSmall ? (p < v) : (p > v)) v = p;
                }
            }
            s_key[tid] = v;
            __syncthreads();
        }
        #pragma unroll
        for (int k = 64; k <= CCAP; k <<= 1) {
            for (int j = k >> 1; j >= 32; j >>= 1) {
                int i = tid, l = i ^ j;
                if (l > i) {
                    unsigned long long A = s_key[i], Bv = s_key[l];
                    bool up = ((i & k) == 0);
                    if ((A > Bv) == up) { s_key[i] = Bv; s_key[l] = A; }
                }
                __syncthreads();
            }
            {
                unsigned long long v = s_key[tid];
                bool up = ((tid & k) == 0);
                #pragma unroll
                for (int j = 16; j > 0; j >>= 1) {
                    unsigned long long p = shflx64(v, j);
                    bool keepSmall = (((tid & j) == 0) == up);
                    if (keepSmall ? (p < v) : (p > v)) v = p;
                }
                s_key[tid] = v;
                __syncthreads();
            }
        }

        // ---- gather boxes/labels; predead vs previous picks; build class masks ----
        const int kc0 = s_kc;
        #pragma unroll
        for (int z = tid; z < NCLS * 8; z += 256) ((unsigned*)s_cmask)[z] = 0u;
        s_alive[tid] = 0;
        __syncthreads();

        if (tid < cN) {
            int idx = (int)(s_key[tid] & 0xFFFFFFFFull);
            float4 mybox = g_boxes[base + idx];
            int mylab = g_labels[base + idx];
            float t = __fmul_rn((float)mylab, off);
            mybox.x = __fadd_rn(mybox.x, t);
            mybox.y = __fadd_rn(mybox.y, t);
            mybox.z = __fadd_rn(mybox.z, t);
            mybox.w = __fadd_rn(mybox.w, t);
            s_box[tid]  = mybox;
            s_lab8[tid] = (unsigned char)mylab;
            int pred = 0;
            for (int j2 = 0; j2 < kc0; ++j2)
                if (s_klab[j2] == (unsigned char)mylab && iou_gt(s_keptb[j2], mybox)) { pred = 1; break; }
            if (!pred)
                atomicOr(&s_cmask[mylab][tid >> 5], 1u << (tid & 31));
        }
        __syncthreads();

        // ---- per-class greedy: 80 independent tiny serial NMS chains in parallel ----
        if (tid < NCLS) {
            unsigned char kl[CCAP];
            int nkl = 0;
            #pragma unroll
            for (int w = 0; w < 8; ++w) {
                unsigned m = s_cmask[tid][w];
                while (m != 0u) {
                    int c = (w << 5) + (__ffs(m) - 1);
                    m &= m - 1u;
                    float4 cb = s_box[c];
                    bool dead = false;
                    for (int j = 0; j < nkl; ++j) {
                        if (iou_gt(s_box[kl[j]], cb)) { dead = true; break; }
                    }
                    if (!dead) {
                        s_alive[c] = 1;
                        kl[nkl++] = (unsigned char)c;
                    }
                }
            }
        }
        __syncthreads();

        // ---- selection: survivor rank via ballots; first (MAXDET-kc0) become picks ----
        {
            unsigned bal = __ballot_sync(0xFFFFFFFFu, s_alive[tid] != 0);
            if (lane == 0) s_abits[wid] = bal;
        }
        __syncthreads();
        {
            int pre = 0;
            #pragma unroll
            for (int w = 0; w < 8; ++w)
                pre += (w < wid) ? __popc(s_abits[w]) : 0;
            if (s_alive[tid]) {
                int rank = pre + __popc(s_abits[wid] & ((lane == 0) ? 0u : (0xFFFFFFFFu >> (32 - lane))));
                int slot = kc0 + rank;
                if (slot < MAXDET) {
                    s_keptb[slot] = s_box[tid];
                    s_klab[slot]  = s_lab8[tid];
                    s_kepti[slot] = (int)(s_key[tid] & 0xFFFFFFFFull);
                }
            }
            if (tid == 0) {
                int tot = 0;
                #pragma unroll
                for (int w = 0; w < 8; ++w) tot += __popc(s_abits[w]);
                int kc = kc0 + tot;
                s_kc = kc > MAXDET ? MAXDET : kc;
            }
        }
        __syncthreads();
    }
    __syncthreads();

    // ---- outputs: boxes | scores | labels | valid ----
    int kc = s_kc;
    float* ob  = out;
    float* osc = out + (size_t)B * MAXDET * 4;
    float* olb = osc + (size_t)B * MAXDET;
    float* ovl = olb + (size_t)B * MAXDET;

    if (tid < MAXDET) {
        int r = tid;
        float4 bx = make_float4(0.f, 0.f, 0.f, 0.f);
        float scv = 0.f, lb = -1.f, vl = 0.f;
        if (r < kc) {
            int idx = s_kepti[r];
            bx = g_boxes[base + idx];
            scv = g_scores[base + idx];
            lb = (float)g_labels[base + idx];
            vl = 1.0f;
        }
        float* obp = ob + ((size_t)b * MAXDET + r) * 4;
        obp[0] = bx.x; obp[1] = bx.y; obp[2] = bx.z; obp[3] = bx.w;
        osc[(size_t)b * MAXDET + r] = scv;
        olb[(size_t)b * MAXDET + r] = lb;
        ovl[(size_t)b * MAXDET + r] = vl;
    }
}

// ---------------- launch ----------------
extern "C" void kernel_launch(void* const* d_in, const int* in_sizes, int n_in,
                              void* d_out, int out_size)
{
    int B = in_sizes[0] / 512000;
    if (B < 1) B = 1;
    if (B > MAXB) B = MAXB;

    const float *cls[3], *reg[3], *obj[3];
    bool grouped = (n_in >= 9) && (in_sizes[1] == B * 128000);
    if (grouped) {
        for (int i = 0; i < 3; ++i) {
            cls[i] = (const float*)d_in[i];
            reg[i] = (const float*)d_in[3 + i];
            obj[i] = (const float*)d_in[6 + i];
        }
    } else {
        for (int i = 0; i < 3; ++i) {
            cls[i] = (const float*)d_in[3 * i];
            reg[i] = (const float*)d_in[3 * i + 1];
            obj[i] = (const float*)d_in[3 * i + 2];
        }
    }

    dim3 gd((2100 + 127) / 128, B);          // pair-per-group: 544 CTAs
    k_decode<<<gd, 256>>>(cls[0], reg[0], obj[0],
                          cls[1], reg[1], obj[1],
                          cls[2], reg[2], obj[2]);
    k_nms<<<B, 256>>>((float*)d_out, B);
}

// round 15
// speedup vs baseline: 1.3967x; 1.1358x over previous
#include <cuda_runtime.h>
#include <math.h>

#define NANCH   8400
#define MAXB    32
#define NCLS    80
#define MAXDET  100
#define NBKT    1024
#define CCAP    256      // chunk capacity (= NMS sort width = blockDim)

// ---------------- device scratch (static zero-init; self-cleaning across graph replays) ----------------
__device__ float  g_scores[MAXB * NANCH];
__device__ float4 g_boxes [MAXB * NANCH];
__device__ int    g_labels[MAXB * NANCH];
__device__ int    g_maxabs[MAXB];
__device__ int    g_hist  [MAXB][NBKT];

__device__ __forceinline__ float sigmoidf_(float x) {
    return 1.0f / (1.0f + expf(-x));
}

__device__ __forceinline__ int score_bucket(float scv) {
    int bkt = (int)(scv * 1024.0f);
    return bkt > NBKT - 1 ? NBKT - 1 : bkt;
}

__device__ __forceinline__ unsigned long long make_key(float scv, unsigned idx) {
    unsigned u = __float_as_uint(scv);
    u = ~(u ^ 0x80000000u);
    return ((unsigned long long)u << 32) | idx;
}

// ---------------- decode: split-class thread pairs + hoisted reg/obj + deep unroll (R13 best) ----------------
__global__ void __launch_bounds__(256) k_decode(
    const float* __restrict__ cls0, const float* __restrict__ reg0, const float* __restrict__ obj0,
    const float* __restrict__ cls1, const float* __restrict__ reg1, const float* __restrict__ obj1,
    const float* __restrict__ cls2, const float* __restrict__ reg2, const float* __restrict__ obj2)
{
    __shared__ int s_h[NBKT];
    const int b    = blockIdx.y;
    const int tid  = threadIdx.x;
    const int half = tid & 1;
    const int g    = blockIdx.x * 128 + (tid >> 1);
    const bool act = (g < NANCH / 4);
    const int gc   = act ? g : (NANCH / 4 - 1);
    const int a    = gc * 4;
    float m4 = 0.0f;

    ((int4*)s_h)[tid] = make_int4(0, 0, 0, 0);
    __syncthreads();

    const float *cls, *reg, *obj;
    int a0, w, hw; float s;
    if (a < 6400)      { cls = cls0; reg = reg0; obj = obj0; a0 = a;        w = 80; hw = 6400; s = 8.0f;  }
    else if (a < 8000) { cls = cls1; reg = reg1; obj = obj1; a0 = a - 6400; w = 40; hw = 1600; s = 16.0f; }
    else               { cls = cls2; reg = reg2; obj = obj2; a0 = a - 8000; w = 20; hw = 400;  s = 32.0f; }

    const int hw4 = hw >> 2;
    const int q   = a0 >> 2;
    const int lb0 = half * 40;

    float4 ov = *((const float4*)(obj + (size_t)b * hw) + q);
    const float* rb = reg + (size_t)b * 4 * hw;
    float4 r0 = *((const float4*)(rb)          + q);
    float4 r1 = *((const float4*)(rb +     hw) + q);
    float4 r2 = *((const float4*)(rb + 2 * hw) + q);
    float4 r3 = *((const float4*)(rb + 3 * hw) + q);

    const float4* c4 = (const float4*)(cls + (size_t)b * NCLS * hw) + (size_t)lb0 * hw4 + q;
    float4 v = c4[0];
    float m0 = v.x, m1 = v.y, m2 = v.z, m3 = v.w;
    int   l0 = lb0, l1 = lb0, l2 = lb0, l3 = lb0;
    #pragma unroll 8
    for (int c = 1; c < 40; ++c) {
        v = c4[(size_t)c * hw4];
        if (v.x > m0) { m0 = v.x; l0 = lb0 + c; }
        if (v.y > m1) { m1 = v.y; l1 = lb0 + c; }
        if (v.z > m2) { m2 = v.z; l2 = lb0 + c; }
        if (v.w > m3) { m3 = v.w; l3 = lb0 + c; }
    }

    float mm[4] = { m0, m1, m2, m3 };
    int   ll[4] = { l0, l1, l2, l3 };
    #pragma unroll
    for (int i = 0; i < 4; ++i) {
        float om = __shfl_xor_sync(0xFFFFFFFFu, mm[i], 1);
        int   ol = __shfl_xor_sync(0xFFFFFFFFu, ll[i], 1);
        float lom = half ? om : mm[i];
        int   lol = half ? ol : ll[i];
        float him = half ? mm[i] : om;
        int   hil = half ? ll[i] : ol;
        if (him > lom) { mm[i] = him; ll[i] = hil; }
        else           { mm[i] = lom; ll[i] = lol; }
    }

    float oo[4] = { ov.x, ov.y, ov.z, ov.w };
    float rx[4] = { r0.x, r0.y, r0.z, r0.w };
    float ry[4] = { r1.x, r1.y, r1.z, r1.w };
    float rw[4] = { r2.x, r2.y, r2.z, r2.w };
    float rh[4] = { r3.x, r3.y, r3.z, r3.w };

    const int i0 = half * 2;
    const size_t mybase = (size_t)b * NANCH + a + i0;
    float sc[2];
    int   lo2[2];
    #pragma unroll
    for (int k = 0; k < 2; ++k) {
        int i = i0 + k;
        sc[k]  = __fmul_rn(sigmoidf_(mm[i]), sigmoidf_(oo[i]));
        lo2[k] = ll[i];
        int ai = a0 + i;
        float px = (float)(ai % w) * s;
        float py = (float)(ai / w) * s;
        float cx = __fadd_rn(__fmul_rn(rx[i], s), px);
        float cy = __fadd_rn(__fmul_rn(ry[i], s), py);
        float bw = __fmul_rn(expf(rw[i]), s);
        float bh = __fmul_rn(expf(rh[i]), s);
        float hx = __fmul_rn(bw, 0.5f);
        float hy = __fmul_rn(bh, 0.5f);
        float x1 = __fsub_rn(cx, hx), y1 = __fsub_rn(cy, hy);
        float x2 = __fadd_rn(cx, hx), y2 = __fadd_rn(cy, hy);
        if (act) {
            g_boxes[mybase + k] = make_float4(x1, y1, x2, y2);
            m4 = fmaxf(m4, fmaxf(fmaxf(fabsf(x1), fabsf(y1)), fmaxf(fabsf(x2), fabsf(y2))));
            if (sc[k] >= 0.01f)
                atomicAdd(&s_h[score_bucket(sc[k])], 1);
        }
    }
    if (act) {
        *((float2*)(g_scores + mybase)) = make_float2(sc[0], sc[1]);
        *((int2*)(g_labels + mybase))   = make_int2(lo2[0], lo2[1]);
    }

    #pragma unroll
    for (int o = 16; o > 0; o >>= 1)
        m4 = fmaxf(m4, __shfl_xor_sync(0xFFFFFFFFu, m4, o));
    if ((threadIdx.x & 31) == 0 && m4 > 0.0f)
        atomicMax(&g_maxabs[b], __float_as_int(m4));

    __syncthreads();
    #pragma unroll
    for (int k = tid; k < NBKT; k += 256) {
        int hv = s_h[k];
        if (hv) atomicAdd(&g_hist[b][k], hv);
    }
}

__device__ __forceinline__ unsigned long long shflx64(unsigned long long v, int j) {
    return __shfl_xor_sync(0xFFFFFFFFu, v, j);
}

// exact reference IoU>thr test on offset boxes
__device__ __forceinline__ bool iou_gt(float4 a, float4 bx) {
    float tlx = fmaxf(a.x, bx.x), tly = fmaxf(a.y, bx.y);
    float brx = fminf(a.z, bx.z), bry = fminf(a.w, bx.w);
    float ww = fmaxf(__fsub_rn(brx, tlx), 0.0f);
    float hh = fmaxf(__fsub_rn(bry, tly), 0.0f);
    float inter = __fmul_rn(ww, hh);
    float a1 = __fmul_rn(__fsub_rn(a.z, a.x), __fsub_rn(a.w, a.y));
    float a2 = __fmul_rn(__fsub_rn(bx.z, bx.x), __fsub_rn(bx.w, bx.y));
    float den = __fadd_rn(__fsub_rn(__fadd_rn(a1, a2), inter), 1e-6f);
    return __fdiv_rn(inter, den) > 0.65f;
}

// Warp-parallel replica of the serial bucket walk. Returns lo for range [lo, hi];
// next ptr = lo - 1. Exactly matches: include buckets top-down while (acc==0 || acc+h<=CCAP),
// stop after acc>=CCAP. Call with warp (32 lanes), hist in smem.
__device__ __forceinline__ int chunk_lo_warp(const int* hist, int hi, int lane) {
    const int top = 1023 - 32 * lane;          // lane's highest bucket (descending coverage)
    int s = 0;
    #pragma unroll
    for (int k = 0; k < 32; ++k) {
        int bkt = top - k;
        s += (bkt <= hi) ? hist[bkt] : 0;
    }
    int cum = s;                                // inclusive scan over lanes: S at lane's lowest bucket
    #pragma unroll
    for (int o = 1; o < 32; o <<= 1) {
        int v = __shfl_up_sync(0xFFFFFFFFu, cum, o);
        if (lane >= o) cum += v;
    }
    int total = __shfl_sync(0xFFFFFFFFu, cum, 31);
    if (total == 0) return 0;                   // nothing in [0,hi]: compact empty, ptr -> -1

    // f = highest nonempty bucket <= hi, hf = hist[f]
    unsigned nz = __ballot_sync(0xFFFFFFFFu, s > 0);
    int lf = __ffs(nz) - 1;
    int f = 0, hf = 0;
    if (lane == lf) {
        #pragma unroll
        for (int k = 0; k < 32; ++k) {
            int bkt = top - k;
            int v = (bkt <= hi) ? hist[bkt] : 0;
            if (v > 0) { f = bkt; hf = v; break; }
        }
    }
    f  = __shfl_sync(0xFFFFFFFFu, f, lf);
    hf = __shfl_sync(0xFFFFFFFFu, hf, lf);
    if (hf >= CCAP) return f;                   // single big bucket: walk includes it alone

    // lo = (largest p with S(p) >= CCAP+1) + 1 ; none -> 0
    unsigned ball = __ballot_sync(0xFFFFFFFFu, cum >= CCAP + 1);
    if (!ball) return 0;
    int l0 = __ffs(ball) - 1;
    int pstar = 0;
    if (lane == l0) {
        int run = cum - s;                      // S exclusive above my range
        #pragma unroll
        for (int k = 0; k < 32; ++k) {
            int bkt = top - k;
            run += (bkt <= hi) ? hist[bkt] : 0;
            if (run >= CCAP + 1) { pstar = bkt; break; }
        }
    }
    pstar = __shfl_sync(0xFFFFFFFFu, pstar, l0);
    return pstar + 1;
}

// ---------------- NMS: prefetch -> warp range -> compact -> sort -> per-class greedy -> rank ----------------
__global__ void __launch_bounds__(256) k_nms(float* __restrict__ out, int B)
{
    __shared__ __align__(16) int                s_hist[NBKT];
    __shared__ __align__(16) unsigned long long s_key[CCAP];
    __shared__ __align__(16) float4             s_box[CCAP];
    __shared__ __align__(16) unsigned           s_cmask[NCLS][8];
    __shared__ __align__(16) unsigned char      s_lab8[CCAP];
    __shared__ __align__(16) unsigned char      s_alive[CCAP];
    __shared__ unsigned           s_abits[8];
    __shared__ float4             s_keptb[MAXDET];
    __shared__ unsigned char      s_klab[MAXDET];
    __shared__ int                s_kepti[MAXDET];
    __shared__ float              s_off;
    __shared__ int                s_cnt, s_kc, s_lo, s_hi, s_ptr;

    const int b    = blockIdx.x;
    const int tid  = threadIdx.x;
    const int wid  = tid >> 5;
    const int lane = tid & 31;
    const size_t base = (size_t)b * NANCH;

    // ---- prefetch ALL scores into registers (cold-DRAM fetch overlaps hist phase) ----
    const float4* sc4 = (const float4*)(g_scores + base);
    float4 pf[9];
    #pragma unroll
    for (int k = 0; k < 8; ++k) pf[k] = sc4[tid + (k << 8)];
    if (tid < NANCH / 4 - 2048) pf[8] = sc4[tid + 2048];

    if (tid == 0) {
        s_off = __fadd_rn(__int_as_float(g_maxabs[b]), 1.0f);
        g_maxabs[b] = 0;
        s_ptr = -1;
        s_kc = 0;
    }
    int4 h4;
    {
        int4* gh4 = (int4*)&g_hist[b][0];
        h4 = gh4[tid];
        ((int4*)s_hist)[tid] = h4;
        gh4[tid] = make_int4(0, 0, 0, 0);
    }
    __syncthreads();
    {
        int maxk = -1;
        if (h4.w) maxk = tid * 4 + 3;
        else if (h4.z) maxk = tid * 4 + 2;
        else if (h4.y) maxk = tid * 4 + 1;
        else if (h4.x) maxk = tid * 4;
        #pragma unroll
        for (int o = 16; o > 0; o >>= 1)
            maxk = max(maxk, __shfl_xor_sync(0xFFFFFFFFu, maxk, o));
        if ((tid & 31) == 0) atomicMax(&s_ptr, maxk);
    }
    __syncthreads();
    const float off = s_off;
    bool first_round = true;

    for (;;) {
        // race-free round control: read -> barrier -> (maybe) write
        bool done = (s_kc >= MAXDET || s_ptr < 0);
        __syncthreads();
        if (done) break;

        if (tid < 32) {
            int hi = s_ptr;
            int lo = chunk_lo_warp(s_hist, hi, lane);
            if (lane == 0) { s_lo = lo; s_hi = hi; s_ptr = lo - 1; s_cnt = 0; }
        }
        __syncthreads();
        const int lo = s_lo, hi = s_hi;

        // ---- compact: round 1 from prefetched registers; later rounds L1-hot reload ----
        if (first_round) {
            #pragma unroll
            for (int k = 0; k < 9; ++k) {
                int i4 = tid + (k << 8);
                if (k == 8 && i4 >= NANCH / 4) break;
                float4 s4 = pf[k];
                float sv[4] = { s4.x, s4.y, s4.z, s4.w };
                #pragma unroll
                for (int t = 0; t < 4; ++t) {
                    float scv = sv[t];
                    if (scv >= 0.01f) {
                        int bkt = score_bucket(scv);
                        if (bkt >= lo && bkt <= hi) {
                            int p = atomicAdd(&s_cnt, 1);
                            if (p < CCAP) s_key[p] = make_key(scv, (unsigned)(i4 * 4 + t));
                        }
                    }
                }
            }
        } else {
            for (int i4 = tid; i4 < NANCH / 4; i4 += 256) {
                float4 s4 = sc4[i4];
                float sv[4] = { s4.x, s4.y, s4.z, s4.w };
                #pragma unroll
                for (int t = 0; t < 4; ++t) {
                    float scv = sv[t];
                    if (scv >= 0.01f) {
                        int bkt = score_bucket(scv);
                        if (bkt >= lo && bkt <= hi) {
                            int p = atomicAdd(&s_cnt, 1);
                            if (p < CCAP) s_key[p] = make_key(scv, (unsigned)(i4 * 4 + t));
                        }
                    }
                }
            }
        }
        first_round = false;
        __syncthreads();
        int cN = s_cnt; if (cN > CCAP) cN = CCAP;
        if (tid >= cN) s_key[tid] = 0xFFFFFFFFFFFFFFFFull;

        // ---- bitonic sort 256 keys ascending (= score desc, idx asc) ----
        {
            unsigned long long v = s_key[tid];
            #pragma unroll
            for (int k = 2; k <= 32; k <<= 1) {
                bool up = ((tid & k) == 0);
                #pragma unroll
                for (int j = k >> 1; j > 0; j >>= 1) {
                    unsigned long long p = shflx64(v, j);
                    bool keepSmall = (((tid & j) == 0) == up);
                    if (keepSmall ? (p < v) : (p > v)) v = p;
                }
            }
            s_key[tid] = v;
            __syncthreads();
        }
        #pragma unroll
        for (int k = 64; k <= CCAP; k <<= 1) {
            for (int j = k >> 1; j >= 32; j >>= 1) {
                int i = tid, l = i ^ j;
                if (l > i) {
                    unsigned long long A = s_key[i], Bv = s_key[l];
                    bool up = ((i & k) == 0);
                    if ((A > Bv) == up) { s_key[i] = Bv; s_key[l] = A; }
                }
                __syncthreads();
            }
            {
                unsigned long long v = s_key[tid];
                bool up = ((tid & k) == 0);
                #pragma unroll
                for (int j = 16; j > 0; j >>= 1) {
                    unsigned long long p = shflx64(v, j);
                    bool keepSmall = (((tid & j) == 0) == up);
                    if (keepSmall ? (p < v) : (p > v)) v = p;
                }
                s_key[tid] = v;
                __syncthreads();
            }
        }

        // ---- gather boxes/labels; predead vs previous picks; build class masks ----
        const int kc0 = s_kc;
        #pragma unroll
        for (int z = tid; z < NCLS * 8; z += 256) ((unsigned*)s_cmask)[z] = 0u;
        s_alive[tid] = 0;
        __syncthreads();

        if (tid < cN) {
            int idx = (int)(s_key[tid] & 0xFFFFFFFFull);
            float4 mybox = g_boxes[base + idx];
            int mylab = g_labels[base + idx];
            float t = __fmul_rn((float)mylab, off);
            mybox.x = __fadd_rn(mybox.x, t);
            mybox.y = __fadd_rn(mybox.y, t);
            mybox.z = __fadd_rn(mybox.z, t);
            mybox.w = __fadd_rn(mybox.w, t);
            s_box[tid]  = mybox;
            s_lab8[tid] = (unsigned char)mylab;
            int pred = 0;
            for (int j2 = 0; j2 < kc0; ++j2)
                if (s_klab[j2] == (unsigned char)mylab && iou_gt(s_keptb[j2], mybox)) { pred = 1; break; }
            if (!pred)
                atomicOr(&s_cmask[mylab][tid >> 5], 1u << (tid & 31));
        }
        __syncthreads();

        // ---- per-class greedy: 80 independent tiny serial NMS chains in parallel ----
        if (tid < NCLS) {
            unsigned char kl[CCAP];
            int nkl = 0;
            #pragma unroll
            for (int w = 0; w < 8; ++w) {
                unsigned m = s_cmask[tid][w];
                while (m != 0u) {
                    int c = (w << 5) + (__ffs(m) - 1);
                    m &= m - 1u;
                    float4 cb = s_box[c];
                    bool dead = false;
                    for (int j = 0; j < nkl; ++j) {
                        if (iou_gt(s_box[kl[j]], cb)) { dead = true; break; }
                    }
                    if (!dead) {
                        s_alive[c] = 1;
                        kl[nkl++] = (unsigned char)c;
                    }
                }
            }
        }
        __syncthreads();

        // ---- selection: survivor rank via ballots; first (MAXDET-kc0) become picks ----
        {
            unsigned bal = __ballot_sync(0xFFFFFFFFu, s_alive[tid] != 0);
            if (lane == 0) s_abits[wid] = bal;
        }
        __syncthreads();
        {
            int pre = 0;
            #pragma unroll
            for (int w = 0; w < 8; ++w)
                pre += (w < wid) ? __popc(s_abits[w]) : 0;
            if (s_alive[tid]) {
                int rank = pre + __popc(s_abits[wid] & ((lane == 0) ? 0u : (0xFFFFFFFFu >> (32 - lane))));
                int slot = kc0 + rank;
                if (slot < MAXDET) {
                    s_keptb[slot] = s_box[tid];
                    s_klab[slot]  = s_lab8[tid];
                    s_kepti[slot] = (int)(s_key[tid] & 0xFFFFFFFFull);
                }
            }
            if (tid == 0) {
                int tot = 0;
                #pragma unroll
                for (int w = 0; w < 8; ++w) tot += __popc(s_abits[w]);
                int kc = kc0 + tot;
                s_kc = kc > MAXDET ? MAXDET : kc;
            }
        }
        __syncthreads();
    }
    __syncthreads();

    // ---- outputs: boxes | scores | labels | valid ----
    int kc = s_kc;
    float* ob  = out;
    float* osc = out + (size_t)B * MAXDET * 4;
    float* olb = osc + (size_t)B * MAXDET;
    float* ovl = olb + (size_t)B * MAXDET;

    if (tid < MAXDET) {
        int r = tid;
        float4 bx = make_float4(0.f, 0.f, 0.f, 0.f);
        float scv = 0.f, lb = -1.f, vl = 0.f;
        if (r < kc) {
            int idx = s_kepti[r];
            bx = g_boxes[base + idx];
            scv = g_scores[base + idx];
            lb = (float)g_labels[base + idx];
            vl = 1.0f;
        }
        float* obp = ob + ((size_t)b * MAXDET + r) * 4;
        obp[0] = bx.x; obp[1] = bx.y; obp[2] = bx.z; obp[3] = bx.w;
        osc[(size_t)b * MAXDET + r] = scv;
        olb[(size_t)b * MAXDET + r] = lb;
        ovl[(size_t)b * MAXDET + r] = vl;
    }
}

// ---------------- launch ----------------
extern "C" void kernel_launch(void* const* d_in, const int* in_sizes, int n_in,
                              void* d_out, int out_size)
{
    int B = in_sizes[0] / 512000;
    if (B < 1) B = 1;
    if (B > MAXB) B = MAXB;

    const float *cls[3], *reg[3], *obj[3];
    bool grouped = (n_in >= 9) && (in_sizes[1] == B * 128000);
    if (grouped) {
        for (int i = 0; i < 3; ++i) {
            cls[i] = (const float*)d_in[i];
            reg[i] = (const float*)d_in[3 + i];
            obj[i] = (const float*)d_in[6 + i];
        }
    } else {
        for (int i = 0; i < 3; ++i) {
            cls[i] = (const float*)d_in[3 * i];
            reg[i] = (const float*)d_in[3 * i + 1];
            obj[i] = (const float*)d_in[3 * i + 2];
        }
    }

    dim3 gd((2100 + 127) / 128, B);          // pair-per-group: 544 CTAs
    k_decode<<<gd, 256>>>(cls[0], reg[0], obj[0],
                          cls[1], reg[1], obj[1],
                          cls[2], reg[2], obj[2]);
    k_nms<<<B, 256>>>((float*)d_out, B);
}

// round 16
// speedup vs baseline: 1.9862x; 1.4221x over previous
#include <cuda_runtime.h>
#include <math.h>

#define NANCH   8400
#define MAXB    32
#define NCLS    80
#define MAXDET  100
#define NBKT    1024
#define CCAP    256      // chunk capacity (= NMS sort width = blockDim)

// ---------------- device scratch (static zero-init; self-cleaning across graph replays) ----------------
__device__ float  g_scores[MAXB * NANCH];
__device__ float4 g_boxes [MAXB * NANCH];
__device__ int    g_labels[MAXB * NANCH];
__device__ int    g_maxabs[MAXB];
__device__ int    g_hist  [MAXB][NBKT];

__device__ __forceinline__ float sigmoidf_(float x) {
    return 1.0f / (1.0f + expf(-x));
}

__device__ __forceinline__ int score_bucket(float scv) {
    int bkt = (int)(scv * 1024.0f);
    return bkt > NBKT - 1 ? NBKT - 1 : bkt;
}

__device__ __forceinline__ unsigned long long make_key(float scv, unsigned idx) {
    unsigned u = __float_as_uint(scv);
    u = ~(u ^ 0x80000000u);
    return ((unsigned long long)u << 32) | idx;
}

// ---------------- decode: split-class thread pairs + hoisted reg/obj + deep unroll (R13 best) ----------------
__global__ void __launch_bounds__(256) k_decode(
    const float* __restrict__ cls0, const float* __restrict__ reg0, const float* __restrict__ obj0,
    const float* __restrict__ cls1, const float* __restrict__ reg1, const float* __restrict__ obj1,
    const float* __restrict__ cls2, const float* __restrict__ reg2, const float* __restrict__ obj2)
{
    __shared__ int s_h[NBKT];
    const int b    = blockIdx.y;
    const int tid  = threadIdx.x;
    const int half = tid & 1;
    const int g    = blockIdx.x * 128 + (tid >> 1);
    const bool act = (g < NANCH / 4);
    const int gc   = act ? g : (NANCH / 4 - 1);
    const int a    = gc * 4;
    float m4 = 0.0f;

    ((int4*)s_h)[tid] = make_int4(0, 0, 0, 0);
    __syncthreads();

    const float *cls, *reg, *obj;
    int a0, w, hw; float s;
    if (a < 6400)      { cls = cls0; reg = reg0; obj = obj0; a0 = a;        w = 80; hw = 6400; s = 8.0f;  }
    else if (a < 8000) { cls = cls1; reg = reg1; obj = obj1; a0 = a - 6400; w = 40; hw = 1600; s = 16.0f; }
    else               { cls = cls2; reg = reg2; obj = obj2; a0 = a - 8000; w = 20; hw = 400;  s = 32.0f; }

    const int hw4 = hw >> 2;
    const int q   = a0 >> 2;
    const int lb0 = half * 40;

    float4 ov = *((const float4*)(obj + (size_t)b * hw) + q);
    const float* rb = reg + (size_t)b * 4 * hw;
    float4 r0 = *((const float4*)(rb)          + q);
    float4 r1 = *((const float4*)(rb +     hw) + q);
    float4 r2 = *((const float4*)(rb + 2 * hw) + q);
    float4 r3 = *((const float4*)(rb + 3 * hw) + q);

    const float4* c4 = (const float4*)(cls + (size_t)b * NCLS * hw) + (size_t)lb0 * hw4 + q;
    float4 v = c4[0];
    float m0 = v.x, m1 = v.y, m2 = v.z, m3 = v.w;
    int   l0 = lb0, l1 = lb0, l2 = lb0, l3 = lb0;
    #pragma unroll 8
    for (int c = 1; c < 40; ++c) {
        v = c4[(size_t)c * hw4];
        if (v.x > m0) { m0 = v.x; l0 = lb0 + c; }
        if (v.y > m1) { m1 = v.y; l1 = lb0 + c; }
        if (v.z > m2) { m2 = v.z; l2 = lb0 + c; }
        if (v.w > m3) { m3 = v.w; l3 = lb0 + c; }
    }

    float mm[4] = { m0, m1, m2, m3 };
    int   ll[4] = { l0, l1, l2, l3 };
    #pragma unroll
    for (int i = 0; i < 4; ++i) {
        float om = __shfl_xor_sync(0xFFFFFFFFu, mm[i], 1);
        int   ol = __shfl_xor_sync(0xFFFFFFFFu, ll[i], 1);
        float lom = half ? om : mm[i];
        int   lol = half ? ol : ll[i];
        float him = half ? mm[i] : om;
        int   hil = half ? ll[i] : ol;
        if (him > lom) { mm[i] = him; ll[i] = hil; }
        else           { mm[i] = lom; ll[i] = lol; }
    }

    float oo[4] = { ov.x, ov.y, ov.z, ov.w };
    float rx[4] = { r0.x, r0.y, r0.z, r0.w };
    float ry[4] = { r1.x, r1.y, r1.z, r1.w };
    float rw[4] = { r2.x, r2.y, r2.z, r2.w };
    float rh[4] = { r3.x, r3.y, r3.z, r3.w };

    const int i0 = half * 2;
    const size_t mybase = (size_t)b * NANCH + a + i0;
    float sc[2];
    int   lo2[2];
    #pragma unroll
    for (int k = 0; k < 2; ++k) {
        int i = i0 + k;
        sc[k]  = __fmul_rn(sigmoidf_(mm[i]), sigmoidf_(oo[i]));
        lo2[k] = ll[i];
        int ai = a0 + i;
        float px = (float)(ai % w) * s;
        float py = (float)(ai / w) * s;
        float cx = __fadd_rn(__fmul_rn(rx[i], s), px);
        float cy = __fadd_rn(__fmul_rn(ry[i], s), py);
        float bw = __fmul_rn(expf(rw[i]), s);
        float bh = __fmul_rn(expf(rh[i]), s);
        float hx = __fmul_rn(bw, 0.5f);
        float hy = __fmul_rn(bh, 0.5f);
        float x1 = __fsub_rn(cx, hx), y1 = __fsub_rn(cy, hy);
        float x2 = __fadd_rn(cx, hx), y2 = __fadd_rn(cy, hy);
        if (act) {
            g_boxes[mybase + k] = make_float4(x1, y1, x2, y2);
            m4 = fmaxf(m4, fmaxf(fmaxf(fabsf(x1), fabsf(y1)), fmaxf(fabsf(x2), fabsf(y2))));
            if (sc[k] >= 0.01f)
                atomicAdd(&s_h[score_bucket(sc[k])], 1);
        }
    }
    if (act) {
        *((float2*)(g_scores + mybase)) = make_float2(sc[0], sc[1]);
        *((int2*)(g_labels + mybase))   = make_int2(lo2[0], lo2[1]);
    }

    #pragma unroll
    for (int o = 16; o > 0; o >>= 1)
        m4 = fmaxf(m4, __shfl_xor_sync(0xFFFFFFFFu, m4, o));
    if ((threadIdx.x & 31) == 0 && m4 > 0.0f)
        atomicMax(&g_maxabs[b], __float_as_int(m4));

    __syncthreads();
    #pragma unroll
    for (int k = tid; k < NBKT; k += 256) {
        int hv = s_h[k];
        if (hv) atomicAdd(&g_hist[b][k], hv);
    }
}

__device__ __forceinline__ unsigned long long shflx64(unsigned long long v, int j) {
    return __shfl_xor_sync(0xFFFFFFFFu, v, j);
}

// exact reference IoU>thr test on offset boxes
__device__ __forceinline__ bool iou_gt(float4 a, float4 bx) {
    float tlx = fmaxf(a.x, bx.x), tly = fmaxf(a.y, bx.y);
    float brx = fminf(a.z, bx.z), bry = fminf(a.w, bx.w);
    float ww = fmaxf(__fsub_rn(brx, tlx), 0.0f);
    float hh = fmaxf(__fsub_rn(bry, tly), 0.0f);
    float inter = __fmul_rn(ww, hh);
    float a1 = __fmul_rn(__fsub_rn(a.z, a.x), __fsub_rn(a.w, a.y));
    float a2 = __fmul_rn(__fsub_rn(bx.z, bx.x), __fsub_rn(bx.w, bx.y));
    float den = __fadd_rn(__fsub_rn(__fadd_rn(a1, a2), inter), 1e-6f);
    return __fdiv_rn(inter, den) > 0.65f;
}

// Warp-parallel bucket-range computation (exact replica of the serial walk semantics).
__device__ __forceinline__ int chunk_lo_warp(const int* hist, int hi, int lane) {
    const int top = 1023 - 32 * lane;
    int s = 0;
    #pragma unroll
    for (int k = 0; k < 32; ++k) {
        int bkt = top - k;
        s += (bkt <= hi) ? hist[bkt] : 0;
    }
    int cum = s;
    #pragma unroll
    for (int o = 1; o < 32; o <<= 1) {
        int v = __shfl_up_sync(0xFFFFFFFFu, cum, o);
        if (lane >= o) cum += v;
    }
    int total = __shfl_sync(0xFFFFFFFFu, cum, 31);
    if (total == 0) return 0;

    unsigned nz = __ballot_sync(0xFFFFFFFFu, s > 0);
    int lf = __ffs(nz) - 1;
    int f = 0, hf = 0;
    if (lane == lf) {
        #pragma unroll
        for (int k = 0; k < 32; ++k) {
            int bkt = top - k;
            int v = (bkt <= hi) ? hist[bkt] : 0;
            if (v > 0) { f = bkt; hf = v; break; }
        }
    }
    f  = __shfl_sync(0xFFFFFFFFu, f, lf);
    hf = __shfl_sync(0xFFFFFFFFu, hf, lf);
    if (hf >= CCAP) return f;

    unsigned ball = __ballot_sync(0xFFFFFFFFu, cum >= CCAP + 1);
    if (!ball) return 0;
    int l0 = __ffs(ball) - 1;
    int pstar = 0;
    if (lane == l0) {
        int run = cum - s;
        #pragma unroll
        for (int k = 0; k < 32; ++k) {
            int bkt = top - k;
            run += (bkt <= hi) ? hist[bkt] : 0;
            if (run >= CCAP + 1) { pstar = bkt; break; }
        }
    }
    pstar = __shfl_sync(0xFFFFFFFFu, pstar, l0);
    return pstar + 1;
}

// ---------------- NMS ----------------
__global__ void __launch_bounds__(256) k_nms(float* __restrict__ out, int B)
{
    __shared__ __align__(16) int                s_hist[NBKT];
    __shared__ __align__(16) unsigned long long s_key[CCAP];
    __shared__ __align__(16) float4             s_box[CCAP];
    __shared__ __align__(16) unsigned           s_cmask[NCLS][8];
    __shared__ __align__(16) unsigned           s_row[CCAP][8];   // same-class earlier suppressors
    __shared__ __align__(16) unsigned char      s_lab8[CCAP];
    __shared__ __align__(16) unsigned char      s_alive[CCAP];
    __shared__ unsigned           s_abits[8];
    __shared__ float4             s_keptb[MAXDET];
    __shared__ unsigned char      s_klab[MAXDET];
    __shared__ int                s_kepti[MAXDET];
    __shared__ float              s_off;
    __shared__ int                s_cnt, s_kc, s_lo, s_hi, s_ptr;

    const int b    = blockIdx.x;
    const int tid  = threadIdx.x;
    const int wid  = tid >> 5;
    const int lane = tid & 31;
    const size_t base = (size_t)b * NANCH;

    // prefetch ALL scores into registers (cold fetch overlaps hist phase)
    const float4* sc4 = (const float4*)(g_scores + base);
    float4 pf[9];
    #pragma unroll
    for (int k = 0; k < 8; ++k) pf[k] = sc4[tid + (k << 8)];
    if (tid < NANCH / 4 - 2048) pf[8] = sc4[tid + 2048];

    if (tid == 0) {
        s_off = __fadd_rn(__int_as_float(g_maxabs[b]), 1.0f);
        g_maxabs[b] = 0;
        s_ptr = -1;
        s_kc = 0;
    }
    int4 h4;
    {
        int4* gh4 = (int4*)&g_hist[b][0];
        h4 = gh4[tid];
        ((int4*)s_hist)[tid] = h4;
        gh4[tid] = make_int4(0, 0, 0, 0);
    }
    __syncthreads();
    {
        int maxk = -1;
        if (h4.w) maxk = tid * 4 + 3;
        else if (h4.z) maxk = tid * 4 + 2;
        else if (h4.y) maxk = tid * 4 + 1;
        else if (h4.x) maxk = tid * 4;
        #pragma unroll
        for (int o = 16; o > 0; o >>= 1)
            maxk = max(maxk, __shfl_xor_sync(0xFFFFFFFFu, maxk, o));
        if ((tid & 31) == 0) atomicMax(&s_ptr, maxk);
    }
    __syncthreads();
    const float off = s_off;
    bool first_round = true;

    for (;;) {
        bool done = (s_kc >= MAXDET || s_ptr < 0);
        __syncthreads();
        if (done) break;

        if (tid < 32) {
            int hi = s_ptr;
            int lo = chunk_lo_warp(s_hist, hi, lane);
            if (lane == 0) { s_lo = lo; s_hi = hi; s_ptr = lo - 1; s_cnt = 0; }
        }
        __syncthreads();
        const int lo = s_lo, hi = s_hi;

        // ---- compact: round 1 from prefetched registers; later rounds reload ----
        if (first_round) {
            #pragma unroll
            for (int k = 0; k < 9; ++k) {
                int i4 = tid + (k << 8);
                if (k == 8 && i4 >= NANCH / 4) break;
                float4 s4 = pf[k];
                float sv[4] = { s4.x, s4.y, s4.z, s4.w };
                #pragma unroll
                for (int t = 0; t < 4; ++t) {
                    float scv = sv[t];
                    if (scv >= 0.01f) {
                        int bkt = score_bucket(scv);
                        if (bkt >= lo && bkt <= hi) {
                            int p = atomicAdd(&s_cnt, 1);
                            if (p < CCAP) s_key[p] = make_key(scv, (unsigned)(i4 * 4 + t));
                        }
                    }
                }
            }
        } else {
            for (int i4 = tid; i4 < NANCH / 4; i4 += 256) {
                float4 s4 = sc4[i4];
                float sv[4] = { s4.x, s4.y, s4.z, s4.w };
                #pragma unroll
                for (int t = 0; t < 4; ++t) {
                    float scv = sv[t];
                    if (scv >= 0.01f) {
                        int bkt = score_bucket(scv);
                        if (bkt >= lo && bkt <= hi) {
                            int p = atomicAdd(&s_cnt, 1);
                            if (p < CCAP) s_key[p] = make_key(scv, (unsigned)(i4 * 4 + t));
                        }
                    }
                }
            }
        }
        first_round = false;
        __syncthreads();
        int cN = s_cnt; if (cN > CCAP) cN = CCAP;
        if (tid >= cN) s_key[tid] = 0xFFFFFFFFFFFFFFFFull;

        // ---- bitonic sort 256 keys ascending (= score desc, idx asc) ----
        {
            unsigned long long v = s_key[tid];
            #pragma unroll
            for (int k = 2; k <= 32; k <<= 1) {
                bool up = ((tid & k) == 0);
                #pragma unroll
                for (int j = k >> 1; j > 0; j >>= 1) {
                    unsigned long long p = shflx64(v, j);
                    bool keepSmall = (((tid & j) == 0) == up);
                    if (keepSmall ? (p < v) : (p > v)) v = p;
                }
            }
            s_key[tid] = v;
            __syncthreads();
        }
        #pragma unroll
        for (int k = 64; k <= CCAP; k <<= 1) {
            for (int j = k >> 1; j >= 32; j >>= 1) {
                int i = tid, l = i ^ j;
                if (l > i) {
                    unsigned long long A = s_key[i], Bv = s_key[l];
                    bool up = ((i & k) == 0);
                    if ((A > Bv) == up) { s_key[i] = Bv; s_key[l] = A; }
                }
                __syncthreads();
            }
            {
                unsigned long long v = s_key[tid];
                bool up = ((tid & k) == 0);
                #pragma unroll
                for (int j = 16; j > 0; j >>= 1) {
                    unsigned long long p = shflx64(v, j);
                    bool keepSmall = (((tid & j) == 0) == up);
                    if (keepSmall ? (p < v) : (p > v)) v = p;
                }
                s_key[tid] = v;
                __syncthreads();
            }
        }

        // ---- gather boxes/labels; predead vs previous picks; build class masks ----
        const int kc0 = s_kc;
        #pragma unroll
        for (int z = tid; z < NCLS * 8; z += 256) ((unsigned*)s_cmask)[z] = 0u;
        s_alive[tid] = 0;
        __syncthreads();

        float4 mybox = make_float4(0.f, 0.f, 0.f, 0.f);
        int    mylab = -1;
        bool   live  = false;
        if (tid < cN) {
            int idx = (int)(s_key[tid] & 0xFFFFFFFFull);
            mybox = g_boxes[base + idx];
            mylab = g_labels[base + idx];
            float t = __fmul_rn((float)mylab, off);
            mybox.x = __fadd_rn(mybox.x, t);
            mybox.y = __fadd_rn(mybox.y, t);
            mybox.z = __fadd_rn(mybox.z, t);
            mybox.w = __fadd_rn(mybox.w, t);
            s_box[tid]  = mybox;
            s_lab8[tid] = (unsigned char)mylab;
            int pred = 0;
            for (int j2 = 0; j2 < kc0; ++j2)
                if (s_klab[j2] == (unsigned char)mylab && iou_gt(s_keptb[j2], mybox)) { pred = 1; break; }
            if (!pred) {
                live = true;
                atomicOr(&s_cmask[mylab][tid >> 5], 1u << (tid & 31));
            }
        }
        __syncthreads();

        // ---- row building: each live candidate computes suppressors among EARLIER same-class members ----
        // (~3 IoUs/thread avg, loads independent -> pipelined; no serial chains)
        if (live) {
            unsigned r[8] = {0,0,0,0,0,0,0,0};
            const int myw = tid >> 5;
            for (int w = 0; w <= myw; ++w) {
                unsigned m = s_cmask[mylab][w];
                if (w == myw) m &= ((tid & 31) == 0) ? 0u : (0xFFFFFFFFu >> (32 - (tid & 31)));
                while (m != 0u) {
                    int j = (w << 5) + (__ffs(m) - 1);
                    m &= m - 1u;
                    if (iou_gt(s_box[j], mybox))
                        r[w] |= (1u << (j & 31));
                }
            }
            uint4* rp = (uint4*)&s_row[tid][0];
            rp[0] = make_uint4(r[0], r[1], r[2], r[3]);
            rp[1] = make_uint4(r[4], r[5], r[6], r[7]);
        }
        __syncthreads();

        // ---- per-class greedy: pure bitmask chains (no FDIV/LDL in the serial path) ----
        if (tid < NCLS) {
            unsigned K[8] = {0,0,0,0,0,0,0,0};
            #pragma unroll
            for (int w = 0; w < 8; ++w) {
                unsigned m = s_cmask[tid][w];
                while (m != 0u) {
                    int c = (w << 5) + (__ffs(m) - 1);
                    m &= m - 1u;
                    const uint4* rp = (const uint4*)&s_row[c][0];
                    uint4 q0 = rp[0], q1 = rp[1];
                    unsigned hit = (q0.x & K[0]) | (q0.y & K[1]) | (q0.z & K[2]) | (q0.w & K[3]) |
                                   (q1.x & K[4]) | (q1.y & K[5]) | (q1.z & K[6]) | (q1.w & K[7]);
                    if (hit == 0u) {
                        K[w] |= (1u << (c & 31));
                        s_alive[c] = 1;
                    }
                }
            }
        }
        __syncthreads();

        // ---- selection: survivor rank via ballots; first (MAXDET-kc0) become picks ----
        {
            unsigned bal = __ballot_sync(0xFFFFFFFFu, s_alive[tid] != 0);
            if (lane == 0) s_abits[wid] = bal;
        }
        __syncthreads();
        {
            int pre = 0;
            #pragma unroll
            for (int w = 0; w < 8; ++w)
                pre += (w < wid) ? __popc(s_abits[w]) : 0;
            if (s_alive[tid]) {
                int rank = pre + __popc(s_abits[wid] & ((lane == 0) ? 0u : (0xFFFFFFFFu >> (32 - lane))));
                int slot = kc0 + rank;
                if (slot < MAXDET) {
                    s_keptb[slot] = s_box[tid];
                    s_klab[slot]  = s_lab8[tid];
                    s_kepti[slot] = (int)(s_key[tid] & 0xFFFFFFFFull);
                }
            }
            if (tid == 0) {
                int tot = 0;
                #pragma unroll
                for (int w = 0; w < 8; ++w) tot += __popc(s_abits[w]);
                int kc = kc0 + tot;
                s_kc = kc > MAXDET ? MAXDET : kc;
            }
        }
        __syncthreads();
    }
    __syncthreads();

    // ---- outputs: boxes | scores | labels | valid ----
    int kc = s_kc;
    float* ob  = out;
    float* osc = out + (size_t)B * MAXDET * 4;
    float* olb = osc + (size_t)B * MAXDET;
    float* ovl = olb + (size_t)B * MAXDET;

    if (tid < MAXDET) {
        int r = tid;
        float4 bx = make_float4(0.f, 0.f, 0.f, 0.f);
        float scv = 0.f, lb = -1.f, vl = 0.f;
        if (r < kc) {
            int idx = s_kepti[r];
            bx = g_boxes[base + idx];
            scv = g_scores[base + idx];
            lb = (float)g_labels[base + idx];
            vl = 1.0f;
        }
        float* obp = ob + ((size_t)b * MAXDET + r) * 4;
        obp[0] = bx.x; obp[1] = bx.y; obp[2] = bx.z; obp[3] = bx.w;
        osc[(size_t)b * MAXDET + r] = scv;
        olb[(size_t)b * MAXDET + r] = lb;
        ovl[(size_t)b * MAXDET + r] = vl;
    }
}

// ---------------- launch ----------------
extern "C" void kernel_launch(void* const* d_in, const int* in_sizes, int n_in,
                              void* d_out, int out_size)
{
    int B = in_sizes[0] / 512000;
    if (B < 1) B = 1;
    if (B > MAXB) B = MAXB;

    const float *cls[3], *reg[3], *obj[3];
    bool grouped = (n_in >= 9) && (in_sizes[1] == B * 128000);
    if (grouped) {
        for (int i = 0; i < 3; ++i) {
            cls[i] = (const float*)d_in[i];
            reg[i] = (const float*)d_in[3 + i];
            obj[i] = (const float*)d_in[6 + i];
        }
    } else {
        for (int i = 0; i < 3; ++i) {
            cls[i] = (const float*)d_in[3 * i];
            reg[i] = (const float*)d_in[3 * i + 1];
            obj[i] = (const float*)d_in[3 * i + 2];
        }
    }

    dim3 gd((2100 + 127) / 128, B);          // pair-per-group: 544 CTAs
    k_decode<<<gd, 256>>>(cls[0], reg[0], obj[0],
                          cls[1], reg[1], obj[1],
                          cls[2], reg[2], obj[2]);
    k_nms<<<B, 256>>>((float*)d_out, B);
}

// round 17
// speedup vs baseline: 1.9878x; 1.0008x over previous
#include <cuda_runtime.h>
#include <math.h>

#define NANCH   8400
#define MAXB    32
#define NCLS    80
#define MAXDET  100
#define NBKT    1024
#define CCAP    128      // chunk capacity (= NMS sort width)
#define NW      4        // mask words per row (CCAP/32)

// ---------------- device scratch (static zero-init; self-cleaning across graph replays) ----------------
__device__ float  g_scores[MAXB * NANCH];
__device__ float4 g_boxes [MAXB * NANCH];
__device__ int    g_labels[MAXB * NANCH];
__device__ int    g_maxabs[MAXB];
__device__ int    g_hist  [MAXB][NBKT];

__device__ __forceinline__ float sigmoidf_(float x) {
    return 1.0f / (1.0f + expf(-x));
}

__device__ __forceinline__ int score_bucket(float scv) {
    int bkt = (int)(scv * 1024.0f);
    return bkt > NBKT - 1 ? NBKT - 1 : bkt;
}

__device__ __forceinline__ unsigned long long make_key(float scv, unsigned idx) {
    unsigned u = __float_as_uint(scv);
    u = ~(u ^ 0x80000000u);
    return ((unsigned long long)u << 32) | idx;
}

// ---------------- decode: split-class thread pairs + hoisted reg/obj + deep unroll (R13 best) ----------------
__global__ void __launch_bounds__(256) k_decode(
    const float* __restrict__ cls0, const float* __restrict__ reg0, const float* __restrict__ obj0,
    const float* __restrict__ cls1, const float* __restrict__ reg1, const float* __restrict__ obj1,
    const float* __restrict__ cls2, const float* __restrict__ reg2, const float* __restrict__ obj2)
{
    __shared__ int s_h[NBKT];
    const int b    = blockIdx.y;
    const int tid  = threadIdx.x;
    const int half = tid & 1;
    const int g    = blockIdx.x * 128 + (tid >> 1);
    const bool act = (g < NANCH / 4);
    const int gc   = act ? g : (NANCH / 4 - 1);
    const int a    = gc * 4;
    float m4 = 0.0f;

    ((int4*)s_h)[tid] = make_int4(0, 0, 0, 0);
    __syncthreads();

    const float *cls, *reg, *obj;
    int a0, w, hw; float s;
    if (a < 6400)      { cls = cls0; reg = reg0; obj = obj0; a0 = a;        w = 80; hw = 6400; s = 8.0f;  }
    else if (a < 8000) { cls = cls1; reg = reg1; obj = obj1; a0 = a - 6400; w = 40; hw = 1600; s = 16.0f; }
    else               { cls = cls2; reg = reg2; obj = obj2; a0 = a - 8000; w = 20; hw = 400;  s = 32.0f; }

    const int hw4 = hw >> 2;
    const int q   = a0 >> 2;
    const int lb0 = half * 40;

    float4 ov = *((const float4*)(obj + (size_t)b * hw) + q);
    const float* rb = reg + (size_t)b * 4 * hw;
    float4 r0 = *((const float4*)(rb)          + q);
    float4 r1 = *((const float4*)(rb +     hw) + q);
    float4 r2 = *((const float4*)(rb + 2 * hw) + q);
    float4 r3 = *((const float4*)(rb + 3 * hw) + q);

    const float4* c4 = (const float4*)(cls + (size_t)b * NCLS * hw) + (size_t)lb0 * hw4 + q;
    float4 v = c4[0];
    float m0 = v.x, m1 = v.y, m2 = v.z, m3 = v.w;
    int   l0 = lb0, l1 = lb0, l2 = lb0, l3 = lb0;
    #pragma unroll 8
    for (int c = 1; c < 40; ++c) {
        v = c4[(size_t)c * hw4];
        if (v.x > m0) { m0 = v.x; l0 = lb0 + c; }
        if (v.y > m1) { m1 = v.y; l1 = lb0 + c; }
        if (v.z > m2) { m2 = v.z; l2 = lb0 + c; }
        if (v.w > m3) { m3 = v.w; l3 = lb0 + c; }
    }

    float mm[4] = { m0, m1, m2, m3 };
    int   ll[4] = { l0, l1, l2, l3 };
    #pragma unroll
    for (int i = 0; i < 4; ++i) {
        float om = __shfl_xor_sync(0xFFFFFFFFu, mm[i], 1);
        int   ol = __shfl_xor_sync(0xFFFFFFFFu, ll[i], 1);
        float lom = half ? om : mm[i];
        int   lol = half ? ol : ll[i];
        float him = half ? mm[i] : om;
        int   hil = half ? ll[i] : ol;
        if (him > lom) { mm[i] = him; ll[i] = hil; }
        else           { mm[i] = lom; ll[i] = lol; }
    }

    float oo[4] = { ov.x, ov.y, ov.z, ov.w };
    float rx[4] = { r0.x, r0.y, r0.z, r0.w };
    float ry[4] = { r1.x, r1.y, r1.z, r1.w };
    float rw[4] = { r2.x, r2.y, r2.z, r2.w };
    float rh[4] = { r3.x, r3.y, r3.z, r3.w };

    const int i0 = half * 2;
    const size_t mybase = (size_t)b * NANCH + a + i0;
    float sc[2];
    int   lo2[2];
    #pragma unroll
    for (int k = 0; k < 2; ++k) {
        int i = i0 + k;
        sc[k]  = __fmul_rn(sigmoidf_(mm[i]), sigmoidf_(oo[i]));
        lo2[k] = ll[i];
        int ai = a0 + i;
        float px = (float)(ai % w) * s;
        float py = (float)(ai / w) * s;
        float cx = __fadd_rn(__fmul_rn(rx[i], s), px);
        float cy = __fadd_rn(__fmul_rn(ry[i], s), py);
        float bw = __fmul_rn(expf(rw[i]), s);
        float bh = __fmul_rn(expf(rh[i]), s);
        float hx = __fmul_rn(bw, 0.5f);
        float hy = __fmul_rn(bh, 0.5f);
        float x1 = __fsub_rn(cx, hx), y1 = __fsub_rn(cy, hy);
        float x2 = __fadd_rn(cx, hx), y2 = __fadd_rn(cy, hy);
        if (act) {
            g_boxes[mybase + k] = make_float4(x1, y1, x2, y2);
            m4 = fmaxf(m4, fmaxf(fmaxf(fabsf(x1), fabsf(y1)), fmaxf(fabsf(x2), fabsf(y2))));
            if (sc[k] >= 0.01f)
                atomicAdd(&s_h[score_bucket(sc[k])], 1);
        }
    }
    if (act) {
        *((float2*)(g_scores + mybase)) = make_float2(sc[0], sc[1]);
        *((int2*)(g_labels + mybase))   = make_int2(lo2[0], lo2[1]);
    }

    #pragma unroll
    for (int o = 16; o > 0; o >>= 1)
        m4 = fmaxf(m4, __shfl_xor_sync(0xFFFFFFFFu, m4, o));
    if ((threadIdx.x & 31) == 0 && m4 > 0.0f)
        atomicMax(&g_maxabs[b], __float_as_int(m4));

    __syncthreads();
    #pragma unroll
    for (int k = tid; k < NBKT; k += 256) {
        int hv = s_h[k];
        if (hv) atomicAdd(&g_hist[b][k], hv);
    }
}

__device__ __forceinline__ unsigned long long shflx64(unsigned long long v, int j) {
    return __shfl_xor_sync(0xFFFFFFFFu, v, j);
}

// exact reference IoU>thr test on offset boxes
__device__ __forceinline__ bool iou_gt(float4 a, float4 bx) {
    float tlx = fmaxf(a.x, bx.x), tly = fmaxf(a.y, bx.y);
    float brx = fminf(a.z, bx.z), bry = fminf(a.w, bx.w);
    float ww = fmaxf(__fsub_rn(brx, tlx), 0.0f);
    float hh = fmaxf(__fsub_rn(bry, tly), 0.0f);
    float inter = __fmul_rn(ww, hh);
    float a1 = __fmul_rn(__fsub_rn(a.z, a.x), __fsub_rn(a.w, a.y));
    float a2 = __fmul_rn(__fsub_rn(bx.z, bx.x), __fsub_rn(bx.w, bx.y));
    float den = __fadd_rn(__fsub_rn(__fadd_rn(a1, a2), inter), 1e-6f);
    return __fdiv_rn(inter, den) > 0.65f;
}

// Warp-parallel bucket-range computation (exact replica of the serial walk semantics, CCAP chunk).
__device__ __forceinline__ int chunk_lo_warp(const int* hist, int hi, int lane) {
    const int top = 1023 - 32 * lane;
    int s = 0;
    #pragma unroll
    for (int k = 0; k < 32; ++k) {
        int bkt = top - k;
        s += (bkt <= hi) ? hist[bkt] : 0;
    }
    int cum = s;
    #pragma unroll
    for (int o = 1; o < 32; o <<= 1) {
        int v = __shfl_up_sync(0xFFFFFFFFu, cum, o);
        if (lane >= o) cum += v;
    }
    int total = __shfl_sync(0xFFFFFFFFu, cum, 31);
    if (total == 0) return 0;

    unsigned nz = __ballot_sync(0xFFFFFFFFu, s > 0);
    int lf = __ffs(nz) - 1;
    int f = 0, hf = 0;
    if (lane == lf) {
        #pragma unroll
        for (int k = 0; k < 32; ++k) {
            int bkt = top - k;
            int v = (bkt <= hi) ? hist[bkt] : 0;
            if (v > 0) { f = bkt; hf = v; break; }
        }
    }
    f  = __shfl_sync(0xFFFFFFFFu, f, lf);
    hf = __shfl_sync(0xFFFFFFFFu, hf, lf);
    if (hf >= CCAP) return f;

    unsigned ball = __ballot_sync(0xFFFFFFFFu, cum >= CCAP + 1);
    if (!ball) return 0;
    int l0 = __ffs(ball) - 1;
    int pstar = 0;
    if (lane == l0) {
        int run = cum - s;
        #pragma unroll
        for (int k = 0; k < 32; ++k) {
            int bkt = top - k;
            run += (bkt <= hi) ? hist[bkt] : 0;
            if (run >= CCAP + 1) { pstar = bkt; break; }
        }
    }
    pstar = __shfl_sync(0xFFFFFFFFu, pstar, l0);
    return pstar + 1;
}

// ---------------- NMS: 128-wide chunks ----------------
__global__ void __launch_bounds__(256) k_nms(float* __restrict__ out, int B)
{
    __shared__ __align__(16) int                s_hist[NBKT];
    __shared__ __align__(16) unsigned long long s_key[CCAP];
    __shared__ __align__(16) float4             s_box[CCAP];
    __shared__ __align__(16) unsigned           s_cmask[NCLS][NW];
    __shared__ __align__(16) unsigned           s_row[CCAP][NW];
    __shared__ __align__(16) unsigned char      s_lab8[CCAP];
    __shared__ __align__(16) unsigned char      s_alive[CCAP];
    __shared__ unsigned           s_abits[NW];
    __shared__ float4             s_keptb[MAXDET];
    __shared__ unsigned char      s_klab[MAXDET];
    __shared__ int                s_kepti[MAXDET];
    __shared__ float              s_off;
    __shared__ int                s_cnt, s_kc, s_lo, s_hi, s_ptr;

    const int b    = blockIdx.x;
    const int tid  = threadIdx.x;
    const int wid  = tid >> 5;
    const int lane = tid & 31;
    const size_t base = (size_t)b * NANCH;

    // prefetch ALL scores into registers (cold fetch overlaps hist phase)
    const float4* sc4 = (const float4*)(g_scores + base);
    float4 pf[9];
    #pragma unroll
    for (int k = 0; k < 8; ++k) pf[k] = sc4[tid + (k << 8)];
    if (tid < NANCH / 4 - 2048) pf[8] = sc4[tid + 2048];

    if (tid == 0) {
        s_off = __fadd_rn(__int_as_float(g_maxabs[b]), 1.0f);
        g_maxabs[b] = 0;
        s_ptr = -1;
        s_kc = 0;
    }
    int4 h4;
    {
        int4* gh4 = (int4*)&g_hist[b][0];
        h4 = gh4[tid];
        ((int4*)s_hist)[tid] = h4;
        gh4[tid] = make_int4(0, 0, 0, 0);
    }
    __syncthreads();
    {
        int maxk = -1;
        if (h4.w) maxk = tid * 4 + 3;
        else if (h4.z) maxk = tid * 4 + 2;
        else if (h4.y) maxk = tid * 4 + 1;
        else if (h4.x) maxk = tid * 4;
        #pragma unroll
        for (int o = 16; o > 0; o >>= 1)
            maxk = max(maxk, __shfl_xor_sync(0xFFFFFFFFu, maxk, o));
        if ((tid & 31) == 0) atomicMax(&s_ptr, maxk);
    }
    __syncthreads();
    const float off = s_off;
    bool first_round = true;

    for (;;) {
        bool done = (s_kc >= MAXDET || s_ptr < 0);
        __syncthreads();
        if (done) break;

        if (tid < 32) {
            int hi = s_ptr;
            int lo = chunk_lo_warp(s_hist, hi, lane);
            if (lane == 0) { s_lo = lo; s_hi = hi; s_ptr = lo - 1; s_cnt = 0; }
        }
        __syncthreads();
        const int lo = s_lo, hi = s_hi;

        // ---- compact: round 1 from prefetched registers; later rounds reload ----
        if (first_round) {
            #pragma unroll
            for (int k = 0; k < 9; ++k) {
                int i4 = tid + (k << 8);
                if (k == 8 && i4 >= NANCH / 4) break;
                float4 s4 = pf[k];
                float sv[4] = { s4.x, s4.y, s4.z, s4.w };
                #pragma unroll
                for (int t = 0; t < 4; ++t) {
                    float scv = sv[t];
                    if (scv >= 0.01f) {
                        int bkt = score_bucket(scv);
                        if (bkt >= lo && bkt <= hi) {
                            int p = atomicAdd(&s_cnt, 1);
                            if (p < CCAP) s_key[p] = make_key(scv, (unsigned)(i4 * 4 + t));
                        }
                    }
                }
            }
        } else {
            for (int i4 = tid; i4 < NANCH / 4; i4 += 256) {
                float4 s4 = sc4[i4];
                float sv[4] = { s4.x, s4.y, s4.z, s4.w };
                #pragma unroll
                for (int t = 0; t < 4; ++t) {
                    float scv = sv[t];
                    if (scv >= 0.01f) {
                        int bkt = score_bucket(scv);
                        if (bkt >= lo && bkt <= hi) {
                            int p = atomicAdd(&s_cnt, 1);
                            if (p < CCAP) s_key[p] = make_key(scv, (unsigned)(i4 * 4 + t));
                        }
                    }
                }
            }
        }
        first_round = false;
        __syncthreads();
        int cN = s_cnt; if (cN > CCAP) cN = CCAP;
        if (tid >= cN && tid < CCAP) s_key[tid] = 0xFFFFFFFFFFFFFFFFull;

        // ---- bitonic sort 128 keys ascending (= score desc, idx asc); warps 0-3 ----
        if (tid < CCAP) {
            unsigned long long v = s_key[tid];
            #pragma unroll
            for (int k = 2; k <= 32; k <<= 1) {
                bool up = ((tid & k) == 0);
                #pragma unroll
                for (int j = k >> 1; j > 0; j >>= 1) {
                    unsigned long long p = shflx64(v, j);
                    bool keepSmall = (((tid & j) == 0) == up);
                    if (keepSmall ? (p < v) : (p > v)) v = p;
                }
            }
            s_key[tid] = v;
        }
        __syncthreads();
        #pragma unroll
        for (int k = 64; k <= CCAP; k <<= 1) {
            for (int j = k >> 1; j >= 32; j >>= 1) {
                int i = tid, l = i ^ j;
                if (l > i && l < CCAP) {
                    unsigned long long A = s_key[i], Bv = s_key[l];
                    bool up = ((i & k) == 0);
                    if ((A > Bv) == up) { s_key[i] = Bv; s_key[l] = A; }
                }
                __syncthreads();
            }
            if (tid < CCAP) {
                unsigned long long v = s_key[tid];
                bool up = ((tid & k) == 0);
                #pragma unroll
                for (int j = 16; j > 0; j >>= 1) {
                    unsigned long long p = shflx64(v, j);
                    bool keepSmall = (((tid & j) == 0) == up);
                    if (keepSmall ? (p < v) : (p > v)) v = p;
                }
                s_key[tid] = v;
            }
            __syncthreads();
        }

        // ---- gather boxes/labels; predead vs previous picks; build class masks ----
        const int kc0 = s_kc;
        #pragma unroll
        for (int z = tid; z < NCLS * NW; z += 256) ((unsigned*)s_cmask)[z] = 0u;
        if (tid < CCAP) s_alive[tid] = 0;
        __syncthreads();

        float4 mybox = make_float4(0.f, 0.f, 0.f, 0.f);
        int    mylab = -1;
        bool   live  = false;
        if (tid < cN) {
            int idx = (int)(s_key[tid] & 0xFFFFFFFFull);
            mybox = g_boxes[base + idx];
            mylab = g_labels[base + idx];
            float t = __fmul_rn((float)mylab, off);
            mybox.x = __fadd_rn(mybox.x, t);
            mybox.y = __fadd_rn(mybox.y, t);
            mybox.z = __fadd_rn(mybox.z, t);
            mybox.w = __fadd_rn(mybox.w, t);
            s_box[tid]  = mybox;
            s_lab8[tid] = (unsigned char)mylab;
            int pred = 0;
            for (int j2 = 0; j2 < kc0; ++j2)
                if (s_klab[j2] == (unsigned char)mylab && iou_gt(s_keptb[j2], mybox)) { pred = 1; break; }
            if (!pred) {
                live = true;
                atomicOr(&s_cmask[mylab][tid >> 5], 1u << (tid & 31));
            }
        }
        __syncthreads();

        // ---- row building: suppressors among EARLIER same-class members (pipelined) ----
        if (live) {
            unsigned r[NW] = {0,0,0,0};
            const int myw = tid >> 5;
            for (int w = 0; w <= myw; ++w) {
                unsigned m = s_cmask[mylab][w];
                if (w == myw) m &= ((tid & 31) == 0) ? 0u : (0xFFFFFFFFu >> (32 - (tid & 31)));
                while (m != 0u) {
                    int j = (w << 5) + (__ffs(m) - 1);
                    m &= m - 1u;
                    if (iou_gt(s_box[j], mybox))
                        r[w] |= (1u << (j & 31));
                }
            }
            *((uint4*)&s_row[tid][0]) = make_uint4(r[0], r[1], r[2], r[3]);
        }
        __syncthreads();

        // ---- per-class greedy: pure bitmask chains ----
        if (tid < NCLS) {
            unsigned K[NW] = {0,0,0,0};
            #pragma unroll
            for (int w = 0; w < NW; ++w) {
                unsigned m = s_cmask[tid][w];
                while (m != 0u) {
                    int c = (w << 5) + (__ffs(m) - 1);
                    m &= m - 1u;
                    uint4 q0 = *((const uint4*)&s_row[c][0]);
                    unsigned hit = (q0.x & K[0]) | (q0.y & K[1]) | (q0.z & K[2]) | (q0.w & K[3]);
                    if (hit == 0u) {
                        K[w] |= (1u << (c & 31));
                        s_alive[c] = 1;
                    }
                }
            }
        }
        __syncthreads();

        // ---- selection: survivor rank via ballots (warps 0-3) ----
        if (tid < CCAP) {
            unsigned bal = __ballot_sync(0xFFFFFFFFu, s_alive[tid] != 0);
            if (lane == 0) s_abits[wid] = bal;
        }
        __syncthreads();
        {
            if (tid < CCAP) {
                int pre = 0;
                #pragma unroll
                for (int w = 0; w < NW; ++w)
                    pre += (w < wid) ? __popc(s_abits[w]) : 0;
                if (s_alive[tid]) {
                    int rank = pre + __popc(s_abits[wid] & ((lane == 0) ? 0u : (0xFFFFFFFFu >> (32 - lane))));
                    int slot = kc0 + rank;
                    if (slot < MAXDET) {
                        s_keptb[slot] = s_box[tid];
                        s_klab[slot]  = s_lab8[tid];
                        s_kepti[slot] = (int)(s_key[tid] & 0xFFFFFFFFull);
                    }
                }
            }
            if (tid == 0) {
                int tot = 0;
                #pragma unroll
                for (int w = 0; w < NW; ++w) tot += __popc(s_abits[w]);
                int kc = kc0 + tot;
                s_kc = kc > MAXDET ? MAXDET : kc;
            }
        }
        __syncthreads();
    }
    __syncthreads();

    // ---- outputs: boxes | scores | labels | valid ----
    int kc = s_kc;
    float* ob  = out;
    float* osc = out + (size_t)B * MAXDET * 4;
    float* olb = osc + (size_t)B * MAXDET;
    float* ovl = olb + (size_t)B * MAXDET;

    if (tid < MAXDET) {
        int r = tid;
        float4 bx = make_float4(0.f, 0.f, 0.f, 0.f);
        float scv = 0.f, lb = -1.f, vl = 0.f;
        if (r < kc) {
            int idx = s_kepti[r];
            bx = g_boxes[base + idx];
            scv = g_scores[base + idx];
            lb = (float)g_labels[base + idx];
            vl = 1.0f;
        }
        float* obp = ob + ((size_t)b * MAXDET + r) * 4;
        obp[0] = bx.x; obp[1] = bx.y; obp[2] = bx.z; obp[3] = bx.w;
        osc[(size_t)b * MAXDET + r] = scv;
        olb[(size_t)b * MAXDET + r] = lb;
        ovl[(size_t)b * MAXDET + r] = vl;
    }
}

// ---------------- launch ----------------
extern "C" void kernel_launch(void* const* d_in, const int* in_sizes, int n_in,
                              void* d_out, int out_size)
{
    int B = in_sizes[0] / 512000;
    if (B < 1) B = 1;
    if (B > MAXB) B = MAXB;

    const float *cls[3], *reg[3], *obj[3];
    bool grouped = (n_in >= 9) && (in_sizes[1] == B * 128000);
    if (grouped) {
        for (int i = 0; i < 3; ++i) {
            cls[i] = (const float*)d_in[i];
            reg[i] = (const float*)d_in[3 + i];
            obj[i] = (const float*)d_in[6 + i];
        }
    } else {
        for (int i = 0; i < 3; ++i) {
            cls[i] = (const float*)d_in[3 * i];
            reg[i] = (const float*)d_in[3 * i + 1];
            obj[i] = (const float*)d_in[3 * i + 2];
        }
    }

    dim3 gd((2100 + 127) / 128, B);          // pair-per-group: 544 CTAs
    k_decode<<<gd, 256>>>(cls[0], reg[0], obj[0],
                          cls[1], reg[1], obj[1],
                          cls[2], reg[2], obj[2]);
    k_nms<<<B, 256>>>((float*)d_out, B);
}